// round 1
// baseline (speedup 1.0000x reference)
#include <cuda_runtime.h>

#define D   256
#define PP  512
#define HH  8
#define DA  64
#define TMAX 65536

// ---------------- device scratch (static, no runtime allocation) ----------------
__device__ float g_patln[PP * D];                 // double-layernormed pattern
__device__ float g_kT[HH * DA * PP];              // K transposed: [h][d][p]
__device__ float g_v [HH * PP * DA];              // V: [h][p][d]
__device__ float g_xn [(size_t)TMAX * D];         // conv+LN output
__device__ float g_q  [(size_t)TMAX * HH * DA];   // q projection
__device__ float g_att[(size_t)TMAX * HH * DA];   // attention output

// ---------------- helpers ----------------
__device__ __forceinline__ float block_reduce_sum256(float v, float* scratch) {
    #pragma unroll
    for (int o = 16; o; o >>= 1) v += __shfl_xor_sync(0xffffffffu, v, o);
    int w = threadIdx.x >> 5;
    if ((threadIdx.x & 31) == 0) scratch[w] = v;
    __syncthreads();
    if (threadIdx.x < 32) {
        float s = (threadIdx.x < 8) ? scratch[threadIdx.x] : 0.f;
        #pragma unroll
        for (int o = 4; o; o >>= 1) s += __shfl_xor_sync(0xffffffffu, s, o);
        if (threadIdx.x == 0) scratch[0] = s;
    }
    __syncthreads();
    float r = scratch[0];
    __syncthreads();
    return r;
}

// ---------------- kernel 1: pattern -> layernorm(layernorm(pattern)) ----------------
__global__ void patln2_kernel(const float* __restrict__ pattern) {
    __shared__ float scr[8];
    int p = blockIdx.x, t = threadIdx.x;
    float v = pattern[p * D + t];
    #pragma unroll
    for (int rep = 0; rep < 2; rep++) {
        float s  = block_reduce_sum256(v, scr);
        float s2 = block_reduce_sum256(v * v, scr);
        float mu  = s * (1.f / D);
        float var = s2 * (1.f / D) - mu * mu;
        v = (v - mu) * rsqrtf(var + 1e-5f);
    }
    g_patln[p * D + t] = v;
}

// ---------------- kernel 2: kv = patln @ wkv.T ; split into kT / v ----------------
__global__ void kv_kernel(const float* __restrict__ wkv) {
    __shared__ float pr[D];
    int p = blockIdx.x, t = threadIdx.x;
    pr[t] = g_patln[p * D + t];
    __syncthreads();
    float acc[4] = {0.f, 0.f, 0.f, 0.f};
    for (int i = 0; i < D; i++) {
        float xv = pr[i];
        #pragma unroll
        for (int u = 0; u < 4; u++)
            acc[u] = fmaf(xv, __ldg(&wkv[(size_t)(t + u * 256) * D + i]), acc[u]);
    }
    #pragma unroll
    for (int u = 0; u < 4; u++) {
        int j = t + u * 256;
        int h = j >> 7, r = j & 127;
        if (r < DA) g_kT[(h * DA + r) * PP + p] = acc[u];
        else        g_v [(h * PP + p) * DA + (r - DA)] = acc[u];
    }
}

// ---------------- kernel 3: causal conv + residual + leakyReLU + layernorm ----------------
// tile: 32 tokens, 256 threads (thread = output channel o)
__global__ void convln_kernel(const float* __restrict__ x,
                              const float* __restrict__ conv_w,
                              const float* __restrict__ conv_b,
                              int L) {
    extern __shared__ float sm[];
    float* xs = sm;              // 34*256 inputs (rows t0-2 .. t0+31)
    float* ys = sm + 34 * D;     // 32*256 conv outputs
    float* st = ys + 32 * D;     // 64 stats
    int t0 = blockIdx.x * 32;
    int tid = threadIdx.x;
    int pos0 = t0 % L;           // position within sequence (tile never crosses seq)
    for (int r = 0; r < 34; r++) {
        float v = 0.f;
        if (pos0 + r - 2 >= 0) v = x[(size_t)(t0 + r - 2) * D + tid];
        xs[r * D + tid] = v;
    }
    __syncthreads();

    float b = conv_b[tid];
    float acc[32];
    #pragma unroll
    for (int m = 0; m < 32; m++) acc[m] = b;

    const float* wr = conv_w + (size_t)tid * (D * 3);
    for (int i = 0; i < D; i++) {
        float w0 = __ldg(wr + 3 * i);
        float w1 = __ldg(wr + 3 * i + 1);
        float w2 = __ldg(wr + 3 * i + 2);
        float xa = xs[i];
        float xb = xs[D + i];
        #pragma unroll
        for (int m = 0; m < 32; m++) {
            float xc = xs[(m + 2) * D + i];
            acc[m] = fmaf(w0, xa, acc[m]);
            acc[m] = fmaf(w1, xb, acc[m]);
            acc[m] = fmaf(w2, xc, acc[m]);
            xa = xb; xb = xc;
        }
    }
    #pragma unroll
    for (int m = 0; m < 32; m++) {
        float v = acc[m] + xs[(m + 2) * D + tid];   // residual
        v = v > 0.f ? v : 0.01f * v;                // leaky relu
        ys[m * D + tid] = v;
    }
    __syncthreads();

    // layernorm per token: 8 warps x 4 tokens each
    int lane = tid & 31, warp = tid >> 5;
    for (int jj = 0; jj < 4; jj++) {
        int m = warp + 8 * jj;
        float s = 0.f, s2 = 0.f;
        #pragma unroll
        for (int q = 0; q < 8; q++) {
            float v = ys[m * D + q * 32 + lane];
            s += v; s2 += v * v;
        }
        #pragma unroll
        for (int o = 16; o; o >>= 1) {
            s  += __shfl_xor_sync(0xffffffffu, s, o);
            s2 += __shfl_xor_sync(0xffffffffu, s2, o);
        }
        if (lane == 0) {
            float mu = s * (1.f / D);
            st[m]      = mu;
            st[32 + m] = rsqrtf(s2 * (1.f / D) - mu * mu + 1e-5f);
        }
    }
    __syncthreads();
    #pragma unroll
    for (int m = 0; m < 32; m++)
        g_xn[(size_t)(t0 + m) * D + tid] = (ys[m * D + tid] - st[m]) * st[32 + m];
}

// ---------------- kernel 4: q = xn @ wq.T ----------------
// tile: 16 tokens, 256 threads (thread covers output cols tid and tid+256)
__global__ void qproj_kernel(const float* __restrict__ wq) {
    __shared__ float xs[16 * D];
    int t0 = blockIdx.x * 16, tid = threadIdx.x;
    for (int r = 0; r < 16; r++) xs[r * D + tid] = g_xn[(size_t)(t0 + r) * D + tid];
    __syncthreads();
    float acc[32];
    #pragma unroll
    for (int i = 0; i < 32; i++) acc[i] = 0.f;
    const float* w0r = wq + (size_t)tid * D;
    const float* w1r = wq + (size_t)(tid + 256) * D;
    for (int i = 0; i < D; i++) {
        float a  = __ldg(w0r + i);
        float bw = __ldg(w1r + i);
        #pragma unroll
        for (int m = 0; m < 16; m++) {
            float xv = xs[m * D + i];
            acc[2 * m]     = fmaf(xv, a,  acc[2 * m]);
            acc[2 * m + 1] = fmaf(xv, bw, acc[2 * m + 1]);
        }
    }
    #pragma unroll
    for (int m = 0; m < 16; m++) {
        g_q[(size_t)(t0 + m) * 512 + tid]       = acc[2 * m];
        g_q[(size_t)(t0 + m) * 512 + tid + 256] = acc[2 * m + 1];
    }
}

// ---------------- kernel 5: attention vs fixed pattern bank ----------------
// grid (T/16, H); tile = 16 tokens, 1 head; smem softmax over P=512
__global__ void attn_kernel() {
    __shared__ float qs[16 * DA];
    __shared__ float sc[16 * PP];
    __shared__ float rinv[16];
    int t0 = blockIdx.x * 16, h = blockIdx.y, tid = threadIdx.x;
    for (int k = 0; k < 4; k++) {
        int idx = k * 256 + tid;
        int m = idx >> 6, d = idx & 63;
        qs[idx] = g_q[(size_t)(t0 + m) * 512 + h * DA + d];
    }
    __syncthreads();
    {   // scores: sc[m][p] = 0.125 * q[m]·k[p]
        float acc[32];
        #pragma unroll
        for (int i = 0; i < 32; i++) acc[i] = 0.f;
        const float* kb = g_kT + (h * DA) * PP;
        for (int d = 0; d < DA; d++) {
            float k0 = __ldg(kb + d * PP + tid);
            float k1 = __ldg(kb + d * PP + tid + 256);
            #pragma unroll
            for (int m = 0; m < 16; m++) {
                float qv = qs[m * DA + d];
                acc[2 * m]     = fmaf(qv, k0, acc[2 * m]);
                acc[2 * m + 1] = fmaf(qv, k1, acc[2 * m + 1]);
            }
        }
        #pragma unroll
        for (int m = 0; m < 16; m++) {
            sc[m * PP + tid]       = 0.125f * acc[2 * m];
            sc[m * PP + tid + 256] = 0.125f * acc[2 * m + 1];
        }
    }
    __syncthreads();
    {   // softmax over p: 8 warps x 2 tokens
        int lane = tid & 31, warp = tid >> 5;
        for (int jj = 0; jj < 2; jj++) {
            int m = warp + 8 * jj;
            float mx = -1e30f;
            #pragma unroll
            for (int q = 0; q < 16; q++) mx = fmaxf(mx, sc[m * PP + q * 32 + lane]);
            #pragma unroll
            for (int o = 16; o; o >>= 1) mx = fmaxf(mx, __shfl_xor_sync(0xffffffffu, mx, o));
            float s = 0.f;
            #pragma unroll
            for (int q = 0; q < 16; q++) {
                float e = __expf(sc[m * PP + q * 32 + lane] - mx);
                sc[m * PP + q * 32 + lane] = e;
                s += e;
            }
            #pragma unroll
            for (int o = 16; o; o >>= 1) s += __shfl_xor_sync(0xffffffffu, s, o);
            if (lane == 0) rinv[m] = 1.f / s;
        }
    }
    __syncthreads();
    {   // out[m][d] = attn[m]·v[:, d]
        int d = tid & 63, mg = tid >> 6;
        float acc[4] = {0.f, 0.f, 0.f, 0.f};
        const float* vb = g_v + (size_t)(h * PP) * DA;
        for (int p = 0; p < PP; p++) {
            float vv = __ldg(vb + p * DA + d);
            #pragma unroll
            for (int j = 0; j < 4; j++)
                acc[j] = fmaf(sc[(mg + 4 * j) * PP + p], vv, acc[j]);
        }
        #pragma unroll
        for (int j = 0; j < 4; j++) {
            int m = mg + 4 * j;
            g_att[(size_t)(t0 + m) * 512 + h * DA + d] = acc[j] * rinv[m];
        }
    }
}

// ---------------- kernel 6: out = LN(att @ wout.T + bout) ----------------
__global__ void outln_kernel(const float* __restrict__ wout,
                             const float* __restrict__ bout,
                             float* __restrict__ out) {
    extern __shared__ float sm[];
    float* as_ = sm;             // 16*512
    float* ys  = sm + 16 * 512;  // 16*256
    float* st  = ys + 16 * D;    // 32
    int t0 = blockIdx.x * 16, tid = threadIdx.x;
    for (int k = 0; k < 32; k++) {
        int idx = k * 256 + tid;
        int r = idx >> 9, c = idx & 511;
        as_[idx] = g_att[(size_t)(t0 + r) * 512 + c];
    }
    __syncthreads();
    float acc[16];
    float b = bout[tid];
    #pragma unroll
    for (int m = 0; m < 16; m++) acc[m] = b;
    const float* wr = wout + (size_t)tid * 512;
    for (int i = 0; i < 512; i++) {
        float w = __ldg(wr + i);
        #pragma unroll
        for (int m = 0; m < 16; m++)
            acc[m] = fmaf(w, as_[m * 512 + i], acc[m]);
    }
    #pragma unroll
    for (int m = 0; m < 16; m++) ys[m * D + tid] = acc[m];
    __syncthreads();

    int lane = tid & 31, warp = tid >> 5;
    for (int jj = 0; jj < 2; jj++) {
        int m = warp + 8 * jj;
        float s = 0.f, s2 = 0.f;
        #pragma unroll
        for (int q = 0; q < 8; q++) {
            float v = ys[m * D + q * 32 + lane];
            s += v; s2 += v * v;
        }
        #pragma unroll
        for (int o = 16; o; o >>= 1) {
            s  += __shfl_xor_sync(0xffffffffu, s, o);
            s2 += __shfl_xor_sync(0xffffffffu, s2, o);
        }
        if (lane == 0) {
            float mu = s * (1.f / D);
            st[m]      = mu;
            st[16 + m] = rsqrtf(s2 * (1.f / D) - mu * mu + 1e-5f);
        }
    }
    __syncthreads();
    #pragma unroll
    for (int m = 0; m < 16; m++)
        out[(size_t)(t0 + m) * D + tid] = (ys[m * D + tid] - st[m]) * st[16 + m];
}

// ---------------- launch ----------------
extern "C" void kernel_launch(void* const* d_in, const int* in_sizes, int n_in,
                              void* d_out, int out_size) {
    const float* x       = (const float*)d_in[0];
    const float* conv_w  = (const float*)d_in[1];
    const float* conv_b  = (const float*)d_in[2];
    const float* pattern = (const float*)d_in[3];
    const float* wq      = (const float*)d_in[4];
    const float* wkv     = (const float*)d_in[5];
    const float* wout    = (const float*)d_in[6];
    const float* bout    = (const float*)d_in[7];
    // d_in[8]: x_offsets (int32, uniform), d_in[9]: n (unused)

    int T = in_sizes[0] / D;        // 65536
    int B = in_sizes[8] - 1;        // 32
    int L = T / B;                  // 2048 (sequence length)

    int convln_smem = (34 * D + 32 * D + 64) * (int)sizeof(float);   // 67840
    int outln_smem  = (16 * 512 + 16 * D + 32) * (int)sizeof(float); // 49280
    cudaFuncSetAttribute(convln_kernel, cudaFuncAttributeMaxDynamicSharedMemorySize, convln_smem);
    cudaFuncSetAttribute(outln_kernel,  cudaFuncAttributeMaxDynamicSharedMemorySize, outln_smem);

    patln2_kernel<<<PP, 256>>>(pattern);
    kv_kernel<<<PP, 256>>>(wkv);
    convln_kernel<<<T / 32, 256, convln_smem>>>(x, conv_w, conv_b, L);
    qproj_kernel<<<T / 16, 256>>>(wq);
    dim3 ag(T / 16, HH);
    attn_kernel<<<ag, 256>>>();
    outln_kernel<<<T / 16, 256, outln_smem>>>(wout, bout, (float*)d_out);
}

// round 2
// speedup vs baseline: 1.0011x; 1.0011x over previous
#include <cuda_runtime.h>

#define D   256
#define PP  512
#define HH  8
#define DA  64
#define TMAX 65536

// ---------------- device scratch (static, no runtime allocation) ----------------
__device__ float g_patln[PP * D];                 // double-layernormed pattern
__device__ float g_kT[HH * DA * PP];              // K transposed: [h][d][p]
__device__ float g_v [HH * PP * DA];              // V: [h][p][d]
__device__ float g_xn [(size_t)TMAX * D];         // conv+LN output
__device__ float g_q  [(size_t)TMAX * HH * DA];   // q projection
__device__ float g_att[(size_t)TMAX * HH * DA];   // attention output

// ---------------- helpers ----------------
__device__ __forceinline__ float block_reduce_sum256(float v, float* scratch) {
    #pragma unroll
    for (int o = 16; o; o >>= 1) v += __shfl_xor_sync(0xffffffffu, v, o);
    int w = threadIdx.x >> 5;
    if ((threadIdx.x & 31) == 0) scratch[w] = v;
    __syncthreads();
    if (threadIdx.x < 32) {
        float s = (threadIdx.x < 8) ? scratch[threadIdx.x] : 0.f;
        #pragma unroll
        for (int o = 4; o; o >>= 1) s += __shfl_xor_sync(0xffffffffu, s, o);
        if (threadIdx.x == 0) scratch[0] = s;
    }
    __syncthreads();
    float r = scratch[0];
    __syncthreads();
    return r;
}

// ---------------- kernel 1: pattern -> layernorm(layernorm(pattern)) ----------------
__global__ void patln2_kernel(const float* __restrict__ pattern) {
    __shared__ float scr[8];
    int p = blockIdx.x, t = threadIdx.x;
    float v = pattern[p * D + t];
    #pragma unroll
    for (int rep = 0; rep < 2; rep++) {
        float s  = block_reduce_sum256(v, scr);
        float s2 = block_reduce_sum256(v * v, scr);
        float mu  = s * (1.f / D);
        float var = s2 * (1.f / D) - mu * mu;
        v = (v - mu) * rsqrtf(var + 1e-5f);
    }
    g_patln[p * D + t] = v;
}

// ---------------- kernel 2: kv = patln @ wkv.T ; split into kT / v ----------------
__global__ void kv_kernel(const float* __restrict__ wkv) {
    __shared__ float pr[D];
    int p = blockIdx.x, t = threadIdx.x;
    pr[t] = g_patln[p * D + t];
    __syncthreads();
    float acc[4] = {0.f, 0.f, 0.f, 0.f};
    for (int i = 0; i < D; i++) {
        float xv = pr[i];
        #pragma unroll
        for (int u = 0; u < 4; u++)
            acc[u] = fmaf(xv, __ldg(&wkv[(size_t)(t + u * 256) * D + i]), acc[u]);
    }
    #pragma unroll
    for (int u = 0; u < 4; u++) {
        int j = t + u * 256;
        int h = j >> 7, r = j & 127;
        if (r < DA) g_kT[(h * DA + r) * PP + p] = acc[u];
        else        g_v [(h * PP + p) * DA + (r - DA)] = acc[u];
    }
}

// ---------------- kernel 3: causal conv + residual + leakyReLU + layernorm ----------------
// tile: 32 tokens, 256 threads (thread = output channel o)
__global__ void convln_kernel(const float* __restrict__ x,
                              const float* __restrict__ conv_w,
                              const float* __restrict__ conv_b,
                              int L) {
    extern __shared__ float sm[];
    float* xs = sm;              // 34*256 inputs (rows t0-2 .. t0+31)
    float* ys = sm + 34 * D;     // 32*256 conv outputs
    float* st = ys + 32 * D;     // 64 stats
    int t0 = blockIdx.x * 32;
    int tid = threadIdx.x;
    int pos0 = t0 % L;           // position within sequence (tile never crosses seq)
    for (int r = 0; r < 34; r++) {
        float v = 0.f;
        if (pos0 + r - 2 >= 0) v = x[(size_t)(t0 + r - 2) * D + tid];
        xs[r * D + tid] = v;
    }
    __syncthreads();

    float b = conv_b[tid];
    float acc[32];
    #pragma unroll
    for (int m = 0; m < 32; m++) acc[m] = b;

    const float* wr = conv_w + (size_t)tid * (D * 3);
    for (int i = 0; i < D; i++) {
        float w0 = __ldg(wr + 3 * i);
        float w1 = __ldg(wr + 3 * i + 1);
        float w2 = __ldg(wr + 3 * i + 2);
        float xa = xs[i];
        float xb = xs[D + i];
        #pragma unroll
        for (int m = 0; m < 32; m++) {
            float xc = xs[(m + 2) * D + i];
            acc[m] = fmaf(w0, xa, acc[m]);
            acc[m] = fmaf(w1, xb, acc[m]);
            acc[m] = fmaf(w2, xc, acc[m]);
            xa = xb; xb = xc;
        }
    }
    #pragma unroll
    for (int m = 0; m < 32; m++) {
        float v = acc[m] + xs[(m + 2) * D + tid];   // residual
        v = v > 0.f ? v : 0.01f * v;                // leaky relu
        ys[m * D + tid] = v;
    }
    __syncthreads();

    // layernorm per token: 8 warps x 4 tokens each
    int lane = tid & 31, warp = tid >> 5;
    for (int jj = 0; jj < 4; jj++) {
        int m = warp + 8 * jj;
        float s = 0.f, s2 = 0.f;
        #pragma unroll
        for (int q = 0; q < 8; q++) {
            float v = ys[m * D + q * 32 + lane];
            s += v; s2 += v * v;
        }
        #pragma unroll
        for (int o = 16; o; o >>= 1) {
            s  += __shfl_xor_sync(0xffffffffu, s, o);
            s2 += __shfl_xor_sync(0xffffffffu, s2, o);
        }
        if (lane == 0) {
            float mu = s * (1.f / D);
            st[m]      = mu;
            st[32 + m] = rsqrtf(s2 * (1.f / D) - mu * mu + 1e-5f);
        }
    }
    __syncthreads();
    #pragma unroll
    for (int m = 0; m < 32; m++)
        g_xn[(size_t)(t0 + m) * D + tid] = (ys[m * D + tid] - st[m]) * st[32 + m];
}

// ---------------- kernel 4: q = xn @ wq.T ----------------
// tile: 16 tokens, 256 threads (thread covers output cols tid and tid+256)
__global__ void qproj_kernel(const float* __restrict__ wq) {
    __shared__ float xs[16 * D];
    int t0 = blockIdx.x * 16, tid = threadIdx.x;
    for (int r = 0; r < 16; r++) xs[r * D + tid] = g_xn[(size_t)(t0 + r) * D + tid];
    __syncthreads();
    float acc[32];
    #pragma unroll
    for (int i = 0; i < 32; i++) acc[i] = 0.f;
    const float* w0r = wq + (size_t)tid * D;
    const float* w1r = wq + (size_t)(tid + 256) * D;
    for (int i = 0; i < D; i++) {
        float a  = __ldg(w0r + i);
        float bw = __ldg(w1r + i);
        #pragma unroll
        for (int m = 0; m < 16; m++) {
            float xv = xs[m * D + i];
            acc[2 * m]     = fmaf(xv, a,  acc[2 * m]);
            acc[2 * m + 1] = fmaf(xv, bw, acc[2 * m + 1]);
        }
    }
    #pragma unroll
    for (int m = 0; m < 16; m++) {
        g_q[(size_t)(t0 + m) * 512 + tid]       = acc[2 * m];
        g_q[(size_t)(t0 + m) * 512 + tid + 256] = acc[2 * m + 1];
    }
}

// ---------------- kernel 5: attention vs fixed pattern bank ----------------
// grid (T/16, H); tile = 16 tokens, 1 head; smem softmax over P=512
__global__ void attn_kernel() {
    __shared__ float qs[16 * DA];
    __shared__ float sc[16 * PP];
    __shared__ float rinv[16];
    int t0 = blockIdx.x * 16, h = blockIdx.y, tid = threadIdx.x;
    for (int k = 0; k < 4; k++) {
        int idx = k * 256 + tid;
        int m = idx >> 6, d = idx & 63;
        qs[idx] = g_q[(size_t)(t0 + m) * 512 + h * DA + d];
    }
    __syncthreads();
    {   // scores: sc[m][p] = 0.125 * q[m]·k[p]
        float acc[32];
        #pragma unroll
        for (int i = 0; i < 32; i++) acc[i] = 0.f;
        const float* kb = g_kT + (h * DA) * PP;
        for (int d = 0; d < DA; d++) {
            float k0 = __ldg(kb + d * PP + tid);
            float k1 = __ldg(kb + d * PP + tid + 256);
            #pragma unroll
            for (int m = 0; m < 16; m++) {
                float qv = qs[m * DA + d];
                acc[2 * m]     = fmaf(qv, k0, acc[2 * m]);
                acc[2 * m + 1] = fmaf(qv, k1, acc[2 * m + 1]);
            }
        }
        #pragma unroll
        for (int m = 0; m < 16; m++) {
            sc[m * PP + tid]       = 0.125f * acc[2 * m];
            sc[m * PP + tid + 256] = 0.125f * acc[2 * m + 1];
        }
    }
    __syncthreads();
    {   // softmax over p: 8 warps x 2 tokens
        int lane = tid & 31, warp = tid >> 5;
        for (int jj = 0; jj < 2; jj++) {
            int m = warp + 8 * jj;
            float mx = -1e30f;
            #pragma unroll
            for (int q = 0; q < 16; q++) mx = fmaxf(mx, sc[m * PP + q * 32 + lane]);
            #pragma unroll
            for (int o = 16; o; o >>= 1) mx = fmaxf(mx, __shfl_xor_sync(0xffffffffu, mx, o));
            float s = 0.f;
            #pragma unroll
            for (int q = 0; q < 16; q++) {
                float e = __expf(sc[m * PP + q * 32 + lane] - mx);
                sc[m * PP + q * 32 + lane] = e;
                s += e;
            }
            #pragma unroll
            for (int o = 16; o; o >>= 1) s += __shfl_xor_sync(0xffffffffu, s, o);
            if (lane == 0) rinv[m] = 1.f / s;
        }
    }
    __syncthreads();
    {   // out[m][d] = attn[m]·v[:, d]
        int d = tid & 63, mg = tid >> 6;
        float acc[4] = {0.f, 0.f, 0.f, 0.f};
        const float* vb = g_v + (size_t)(h * PP) * DA;
        for (int p = 0; p < PP; p++) {
            float vv = __ldg(vb + p * DA + d);
            #pragma unroll
            for (int j = 0; j < 4; j++)
                acc[j] = fmaf(sc[(mg + 4 * j) * PP + p], vv, acc[j]);
        }
        #pragma unroll
        for (int j = 0; j < 4; j++) {
            int m = mg + 4 * j;
            g_att[(size_t)(t0 + m) * 512 + h * DA + d] = acc[j] * rinv[m];
        }
    }
}

// ---------------- kernel 6: out = LN(att @ wout.T + bout) ----------------
__global__ void outln_kernel(const float* __restrict__ wout,
                             const float* __restrict__ bout,
                             float* __restrict__ out) {
    extern __shared__ float sm[];
    float* as_ = sm;             // 16*512
    float* ys  = sm + 16 * 512;  // 16*256
    float* st  = ys + 16 * D;    // 32
    int t0 = blockIdx.x * 16, tid = threadIdx.x;
    for (int k = 0; k < 32; k++) {
        int idx = k * 256 + tid;
        int r = idx >> 9, c = idx & 511;
        as_[idx] = g_att[(size_t)(t0 + r) * 512 + c];
    }
    __syncthreads();
    float acc[16];
    float b = bout[tid];
    #pragma unroll
    for (int m = 0; m < 16; m++) acc[m] = b;
    const float* wr = wout + (size_t)tid * 512;
    for (int i = 0; i < 512; i++) {
        float w = __ldg(wr + i);
        #pragma unroll
        for (int m = 0; m < 16; m++)
            acc[m] = fmaf(w, as_[m * 512 + i], acc[m]);
    }
    #pragma unroll
    for (int m = 0; m < 16; m++) ys[m * D + tid] = acc[m];
    __syncthreads();

    int lane = tid & 31, warp = tid >> 5;
    for (int jj = 0; jj < 2; jj++) {
        int m = warp + 8 * jj;
        float s = 0.f, s2 = 0.f;
        #pragma unroll
        for (int q = 0; q < 8; q++) {
            float v = ys[m * D + q * 32 + lane];
            s += v; s2 += v * v;
        }
        #pragma unroll
        for (int o = 16; o; o >>= 1) {
            s  += __shfl_xor_sync(0xffffffffu, s, o);
            s2 += __shfl_xor_sync(0xffffffffu, s2, o);
        }
        if (lane == 0) {
            float mu = s * (1.f / D);
            st[m]      = mu;
            st[16 + m] = rsqrtf(s2 * (1.f / D) - mu * mu + 1e-5f);
        }
    }
    __syncthreads();
    #pragma unroll
    for (int m = 0; m < 16; m++)
        out[(size_t)(t0 + m) * D + tid] = (ys[m * D + tid] - st[m]) * st[16 + m];
}

// ---------------- launch ----------------
extern "C" void kernel_launch(void* const* d_in, const int* in_sizes, int n_in,
                              void* d_out, int out_size) {
    const float* x       = (const float*)d_in[0];
    const float* conv_w  = (const float*)d_in[1];
    const float* conv_b  = (const float*)d_in[2];
    const float* pattern = (const float*)d_in[3];
    const float* wq      = (const float*)d_in[4];
    const float* wkv     = (const float*)d_in[5];
    const float* wout    = (const float*)d_in[6];
    const float* bout    = (const float*)d_in[7];
    // d_in[8]: x_offsets (int32, uniform), d_in[9]: n (unused)

    int T = in_sizes[0] / D;        // 65536
    int B = in_sizes[8] - 1;        // 32
    int L = T / B;                  // 2048 (sequence length)

    int convln_smem = (34 * D + 32 * D + 64) * (int)sizeof(float);   // 67840
    int outln_smem  = (16 * 512 + 16 * D + 32) * (int)sizeof(float); // 49280
    cudaFuncSetAttribute(convln_kernel, cudaFuncAttributeMaxDynamicSharedMemorySize, convln_smem);
    cudaFuncSetAttribute(outln_kernel,  cudaFuncAttributeMaxDynamicSharedMemorySize, outln_smem);

    patln2_kernel<<<PP, 256>>>(pattern);
    kv_kernel<<<PP, 256>>>(wkv);
    convln_kernel<<<T / 32, 256, convln_smem>>>(x, conv_w, conv_b, L);
    qproj_kernel<<<T / 16, 256>>>(wq);
    dim3 ag(T / 16, HH);
    attn_kernel<<<ag, 256>>>();
    outln_kernel<<<T / 16, 256, outln_smem>>>(wout, bout, (float*)d_out);
}

// round 3
// speedup vs baseline: 1.3967x; 1.3952x over previous
#include <cuda_runtime.h>

#define D   256
#define PP  512
#define HH  8
#define DA  64
#define TMAX 65536
typedef unsigned long long u64;

// ---------------- device scratch ----------------
__device__ float g_patln[PP * D];
__device__ float g_kT[HH * DA * PP];              // [h*64+d][p]
__device__ float g_v [HH * PP * DA];              // [h*512+p][d]
__device__ float g_xn [(size_t)TMAX * D];
__device__ float g_att[(size_t)TMAX * HH * DA];
__device__ float g_wqT  [D * 512];                // [k][j]
__device__ float g_woutT[512 * D];                // [k][c]
__device__ float g_cwT  [3 * D * D];              // [tap][i][c]
__device__ float g_wkvT [D * 1024];               // [k][j]

// ---------------- f32x2 helpers ----------------
__device__ __forceinline__ u64 pack2(float x, float y) {
    u64 r; asm("mov.b64 %0,{%1,%2};" : "=l"(r) : "f"(x), "f"(y)); return r;
}
__device__ __forceinline__ u64 dup2(float x) { return pack2(x, x); }
__device__ __forceinline__ void fma2(u64& d, u64 a, u64 b) {
    asm("fma.rn.f32x2 %0,%1,%2,%0;" : "+l"(d) : "l"(a), "l"(b));
}
__device__ __forceinline__ float2 u2f(u64 v) {
    float2 f; asm("mov.b64 {%0,%1},%2;" : "=f"(f.x), "=f"(f.y) : "l"(v)); return f;
}

// ---------------- tiny prep kernels ----------------
__device__ __forceinline__ float block_reduce_sum256(float v, float* scratch) {
    #pragma unroll
    for (int o = 16; o; o >>= 1) v += __shfl_xor_sync(0xffffffffu, v, o);
    int w = threadIdx.x >> 5;
    if ((threadIdx.x & 31) == 0) scratch[w] = v;
    __syncthreads();
    if (threadIdx.x < 32) {
        float s = (threadIdx.x < 8) ? scratch[threadIdx.x] : 0.f;
        #pragma unroll
        for (int o = 4; o; o >>= 1) s += __shfl_xor_sync(0xffffffffu, s, o);
        if (threadIdx.x == 0) scratch[0] = s;
    }
    __syncthreads();
    float r = scratch[0];
    __syncthreads();
    return r;
}

__global__ void patln2_kernel(const float* __restrict__ pattern) {
    __shared__ float scr[8];
    int p = blockIdx.x, t = threadIdx.x;
    float v = pattern[p * D + t];
    #pragma unroll
    for (int rep = 0; rep < 2; rep++) {
        float s  = block_reduce_sum256(v, scr);
        float s2 = block_reduce_sum256(v * v, scr);
        float mu  = s * (1.f / D);
        float var = s2 * (1.f / D) - mu * mu;
        v = (v - mu) * rsqrtf(var + 1e-5f);
    }
    g_patln[p * D + t] = v;
}

__global__ void twq_kernel(const float* __restrict__ wq) {      // grid 256, block 512
    g_wqT[blockIdx.x * 512 + threadIdx.x] = wq[threadIdx.x * 256 + blockIdx.x];
}
__global__ void twout_kernel(const float* __restrict__ wout) {  // grid 512, block 256
    g_woutT[blockIdx.x * 256 + threadIdx.x] = wout[threadIdx.x * 512 + blockIdx.x];
}
__global__ void twkv_kernel(const float* __restrict__ wkv) {    // grid 256, block 1024
    g_wkvT[blockIdx.x * 1024 + threadIdx.x] = wkv[(size_t)threadIdx.x * 256 + blockIdx.x];
}
__global__ void tcw_kernel(const float* __restrict__ cw) {      // grid (256,3), block 256
    int i = blockIdx.x, tap = blockIdx.y, c = threadIdx.x;
    g_cwT[tap * 65536 + i * 256 + c] = cw[c * 768 + i * 3 + tap];
}

// kv = patln @ wkv.T : block = pattern p, thread covers 4 output cols
__global__ void kv_kernel() {
    __shared__ float pr[D];
    int p = blockIdx.x, t = threadIdx.x;
    pr[t] = g_patln[p * D + t];
    __syncthreads();
    float acc[4] = {0.f, 0.f, 0.f, 0.f};
    for (int i = 0; i < D; i++) {
        float xv = pr[i];
        const float* wr = g_wkvT + i * 1024 + t;
        #pragma unroll
        for (int u = 0; u < 4; u++) acc[u] = fmaf(xv, wr[u * 256], acc[u]);
    }
    #pragma unroll
    for (int u = 0; u < 4; u++) {
        int j = t + u * 256;
        int h = j >> 7, r = j & 127;
        if (r < DA) g_kT[(h * DA + r) * PP + p] = acc[u];
        else        g_v [(h * PP + p) * DA + (r - DA)] = acc[u];
    }
}

// ---------------- conv + residual + leaky + LN ----------------
__global__ void convln_kernel(const float* __restrict__ x,
                              const float* __restrict__ conv_b, int L) {
    extern __shared__ float sm[];
    float* xs = sm;              // [34][256]
    float* ys = sm + 34 * D;     // [32][256]
    float* st = ys + 32 * D;     // 64
    int t0 = blockIdx.x * 32, tid = threadIdx.x;
    int pos0 = t0 % L;
    for (int r = 0; r < 34; r++) {
        float v = 0.f;
        if (pos0 + r >= 2) v = x[(size_t)(t0 + r - 2) * D + tid];
        xs[r * D + tid] = v;
    }
    __syncthreads();

    float acc[32];
    float b = __ldg(&conv_b[tid]);
    #pragma unroll
    for (int m = 0; m < 32; m++) acc[m] = b;

    for (int i = 0; i < D; i++) {
        float w0 = __ldg(&g_cwT[          i * 256 + tid]);   // coalesced
        float w1 = __ldg(&g_cwT[ 65536 + i * 256 + tid]);
        float w2 = __ldg(&g_cwT[131072 + i * 256 + tid]);
        float xa = xs[i], xb = xs[D + i];
        #pragma unroll
        for (int m = 0; m < 32; m++) {
            float xc = xs[(m + 2) * D + i];
            acc[m] = fmaf(w0, xa, acc[m]);
            acc[m] = fmaf(w1, xb, acc[m]);
            acc[m] = fmaf(w2, xc, acc[m]);
            xa = xb; xb = xc;
        }
    }
    #pragma unroll
    for (int m = 0; m < 32; m++) {
        float v = acc[m] + xs[(m + 2) * D + tid];
        v = v > 0.f ? v : 0.01f * v;
        ys[m * D + tid] = v;
    }
    __syncthreads();

    int lane = tid & 31, warp = tid >> 5;
    for (int jj = 0; jj < 4; jj++) {
        int m = warp + 8 * jj;
        float s = 0.f, s2 = 0.f;
        #pragma unroll
        for (int q = 0; q < 8; q++) {
            float v = ys[m * D + q * 32 + lane];
            s += v; s2 += v * v;
        }
        #pragma unroll
        for (int o = 16; o; o >>= 1) {
            s  += __shfl_xor_sync(0xffffffffu, s, o);
            s2 += __shfl_xor_sync(0xffffffffu, s2, o);
        }
        if (lane == 0) {
            float mu = s * (1.f / D);
            st[m]      = mu;
            st[32 + m] = rsqrtf(s2 * (1.f / D) - mu * mu + 1e-5f);
        }
    }
    __syncthreads();
    #pragma unroll
    for (int m = 0; m < 32; m++)
        g_xn[(size_t)(t0 + m) * D + tid] = (ys[m * D + tid] - st[m]) * st[32 + m];
}

// ---------------- fused qproj + attention ----------------
// grid (T/32, 8); 256 threads; lane = token, warp = column/pattern slice
__global__ __launch_bounds__(256, 2) void attn_kernel() {
    extern __shared__ float sm[];
    float* qT  = sm;            // [64][33]  (reused as attS [32][65] at end)
    float* pr1 = sm + 2112;     // [8][32]
    float* pr2 = sm + 2368;     // [8][32]
    float* buf = sm + 2624;     // 16896 floats: xnT [256][33] then probs [512][33]
    int tid = threadIdx.x, lane = tid & 31, w = tid >> 5;
    int t0 = blockIdx.x * 32, h = blockIdx.y;

    // stage xnT[k][tok]
    float* xnT = buf;
    for (int r = 0; r < 32; r++) xnT[tid * 33 + r] = g_xn[(size_t)(t0 + r) * D + tid];
    __syncthreads();

    // phase 1: q (cols h*64 + w*8 .. +7)
    u64 qa[4] = {0, 0, 0, 0};
    const float* wqp = g_wqT + h * 64 + w * 8;
    #pragma unroll 4
    for (int k = 0; k < 256; k++) {
        u64 xd = dup2(xnT[k * 33 + lane]);
        const ulonglong2* wp = (const ulonglong2*)(wqp + k * 512);
        ulonglong2 a = wp[0], bq = wp[1];
        fma2(qa[0], a.x, xd); fma2(qa[1], a.y, xd);
        fma2(qa[2], bq.x, xd); fma2(qa[3], bq.y, xd);
    }
    #pragma unroll
    for (int j = 0; j < 4; j++) {
        float2 f = u2f(qa[j]);
        qT[(w * 8 + 2 * j)     * 33 + lane] = f.x;
        qT[(w * 8 + 2 * j + 1) * 33 + lane] = f.y;
    }
    __syncthreads();

    // phase 2: scores for pats w*64 .. w*64+63 (packed pairs)
    u64 sa[32];
    #pragma unroll
    for (int j = 0; j < 32; j++) sa[j] = 0;
    const float* kh = g_kT + (size_t)h * DA * PP + w * 64;
    for (int d = 0; d < DA; d++) {
        u64 qd = dup2(qT[d * 33 + lane]);
        const ulonglong2* kp = (const ulonglong2*)(kh + d * PP);
        #pragma unroll
        for (int j = 0; j < 16; j++) {
            ulonglong2 a = kp[j];
            fma2(sa[2 * j], a.x, qd); fma2(sa[2 * j + 1], a.y, qd);
        }
    }

    // phase 3: softmax across warps (per token = lane)
    float mx = -1e30f;
    #pragma unroll
    for (int j = 0; j < 32; j++) {
        float2 f = u2f(sa[j]);
        mx = fmaxf(mx, fmaxf(f.x, f.y));
    }
    pr1[w * 32 + lane] = mx;
    __syncthreads();
    float gmax = pr1[lane];
    #pragma unroll
    for (int ww = 1; ww < 8; ww++) gmax = fmaxf(gmax, pr1[ww * 32 + lane]);
    float smx = 0.125f * gmax;
    float* probs = buf;          // xnT dead
    float ssum = 0.f;
    #pragma unroll
    for (int j = 0; j < 32; j++) {
        float2 f = u2f(sa[j]);
        float e0 = __expf(fmaf(0.125f, f.x, -smx));
        float e1 = __expf(fmaf(0.125f, f.y, -smx));
        ssum += e0 + e1;
        probs[(w * 64 + 2 * j)     * 33 + lane] = e0;
        probs[(w * 64 + 2 * j + 1) * 33 + lane] = e1;
    }
    pr2[w * 32 + lane] = ssum;
    __syncthreads();
    float Ssum = 0.f;
    #pragma unroll
    for (int ww = 0; ww < 8; ww++) Ssum += pr2[ww * 32 + lane];
    float rinv = 1.f / Ssum;

    // phase 4: PV (d-slice w*8..+7)
    u64 va[4] = {0, 0, 0, 0};
    const float* vh = g_v + (size_t)h * PP * DA + w * 8;
    #pragma unroll 4
    for (int p = 0; p < PP; p++) {
        u64 pd = dup2(probs[p * 33 + lane]);
        const ulonglong2* vp = (const ulonglong2*)(vh + p * 64);
        ulonglong2 a = vp[0], bq = vp[1];
        fma2(va[0], a.x, pd); fma2(va[1], a.y, pd);
        fma2(va[2], bq.x, pd); fma2(va[3], bq.y, pd);
    }
    // stage (token-major) then coalesced write
    float* attS = qT;            // [32][65], 2080 <= 2112
    #pragma unroll
    for (int j = 0; j < 4; j++) {
        float2 f = u2f(va[j]);
        attS[lane * 65 + w * 8 + 2 * j]     = f.x * rinv;
        attS[lane * 65 + w * 8 + 2 * j + 1] = f.y * rinv;
    }
    __syncthreads();
    for (int k = 0; k < 8; k++) {
        int idx = k * 256 + tid, tok = idx >> 6, c = idx & 63;
        g_att[(size_t)(t0 + tok) * 512 + h * 64 + c] = attS[tok * 65 + c];
    }
}

// ---------------- out projection + final LN ----------------
__global__ __launch_bounds__(256, 2) void outln_kernel(const float* __restrict__ bout,
                                                       float* __restrict__ out) {
    extern __shared__ float sm[];
    float* attT = sm;            // [512][33]
    float* ys   = sm + 16896;    // [32][257]
    float* psum = sm + 16896 + 8224;        // [8][32]
    float* psq  = psum + 256;               // [8][32]
    int tid = threadIdx.x, lane = tid & 31, w = tid >> 5;
    int t0 = blockIdx.x * 32;

    for (int r = 0; r < 32; r++) {
        attT[ tid        * 33 + r] = g_att[(size_t)(t0 + r) * 512 + tid];
        attT[(tid + 256) * 33 + r] = g_att[(size_t)(t0 + r) * 512 + tid + 256];
    }
    __syncthreads();

    u64 acc[16];
    #pragma unroll
    for (int j = 0; j < 16; j++) acc[j] = 0;
    const float* wp0 = g_woutT + w * 32;
    #pragma unroll 2
    for (int k = 0; k < 512; k++) {
        u64 xd = dup2(attT[k * 33 + lane]);
        const ulonglong2* wp = (const ulonglong2*)(wp0 + k * 256);
        #pragma unroll
        for (int j = 0; j < 8; j++) {
            ulonglong2 a = wp[j];
            fma2(acc[2 * j], a.x, xd); fma2(acc[2 * j + 1], a.y, xd);
        }
    }
    float vals[32];
    float s = 0.f, s2 = 0.f;
    #pragma unroll
    for (int j = 0; j < 16; j++) {
        float2 f = u2f(acc[j]);
        int c = w * 32 + 2 * j;
        float v0 = f.x + __ldg(&bout[c]);
        float v1 = f.y + __ldg(&bout[c + 1]);
        vals[2 * j] = v0; vals[2 * j + 1] = v1;
        s += v0 + v1; s2 += v0 * v0 + v1 * v1;
    }
    psum[w * 32 + lane] = s;
    psq [w * 32 + lane] = s2;
    __syncthreads();
    float S = 0.f, S2 = 0.f;
    #pragma unroll
    for (int ww = 0; ww < 8; ww++) { S += psum[ww * 32 + lane]; S2 += psq[ww * 32 + lane]; }
    float mu = S * (1.f / D);
    float rstd = rsqrtf(S2 * (1.f / D) - mu * mu + 1e-5f);
    #pragma unroll
    for (int j = 0; j < 32; j++) ys[lane * 257 + w * 32 + j] = (vals[j] - mu) * rstd;
    __syncthreads();
    for (int k = 0; k < 32; k++) {
        int idx = k * 256 + tid, tok = idx >> 8, c = idx & 255;
        out[(size_t)(t0 + tok) * 256 + c] = ys[tok * 257 + c];
    }
}

// ---------------- launch ----------------
extern "C" void kernel_launch(void* const* d_in, const int* in_sizes, int n_in,
                              void* d_out, int out_size) {
    const float* x       = (const float*)d_in[0];
    const float* conv_w  = (const float*)d_in[1];
    const float* conv_b  = (const float*)d_in[2];
    const float* pattern = (const float*)d_in[3];
    const float* wq      = (const float*)d_in[4];
    const float* wkv     = (const float*)d_in[5];
    const float* wout    = (const float*)d_in[6];
    const float* bout    = (const float*)d_in[7];

    int T = in_sizes[0] / D;
    int B = in_sizes[8] - 1;
    int L = T / B;

    int convln_smem = (34 * D + 32 * D + 64) * 4;                 // 67840
    int attn_smem   = (2112 + 256 + 256 + 16896) * 4;             // 78080
    int outln_smem  = (16896 + 8224 + 512) * 4;                   // 102528
    cudaFuncSetAttribute(convln_kernel, cudaFuncAttributeMaxDynamicSharedMemorySize, convln_smem);
    cudaFuncSetAttribute(attn_kernel,   cudaFuncAttributeMaxDynamicSharedMemorySize, attn_smem);
    cudaFuncSetAttribute(outln_kernel,  cudaFuncAttributeMaxDynamicSharedMemorySize, outln_smem);

    patln2_kernel<<<PP, 256>>>(pattern);
    twq_kernel  <<<256, 512>>>(wq);
    twout_kernel<<<512, 256>>>(wout);
    twkv_kernel <<<256, 1024>>>(wkv);
    dim3 cg(256, 3);
    tcw_kernel  <<<cg, 256>>>(conv_w);
    kv_kernel   <<<PP, 256>>>();
    convln_kernel<<<T / 32, 256, convln_smem>>>(x, conv_b, L);
    dim3 ag(T / 32, HH);
    attn_kernel <<<ag, 256, attn_smem>>>();
    outln_kernel<<<T / 32, 256, outln_smem>>>(bout, (float*)d_out);
}

// round 5
// speedup vs baseline: 1.4178x; 1.0151x over previous
#include <cuda_runtime.h>

#define D   256
#define PP  512
#define HH  8
#define DA  64
#define TMAX 65536
typedef unsigned long long u64;

// ---------------- device scratch ----------------
__device__ float g_kT[HH * DA * PP];              // [h*64+d][p]
__device__ float g_v [HH * PP * DA];              // [h*512+p][d]
__device__ float g_xn [(size_t)TMAX * D];
__device__ float g_att[(size_t)TMAX * HH * DA];
__device__ float g_wqT  [D * 512];                // [k][j]
__device__ float g_woutT[512 * D];                // [k][c]
__device__ float g_cwT  [3 * D * D];              // [tap][i][c]
__device__ float g_wkvT [D * 1024];               // [k][j]

// ---------------- f32x2 helpers ----------------
__device__ __forceinline__ u64 pack2(float x, float y) {
    u64 r; asm("mov.b64 %0,{%1,%2};" : "=l"(r) : "f"(x), "f"(y)); return r;
}
__device__ __forceinline__ u64 dup2(float x) { return pack2(x, x); }
__device__ __forceinline__ void fma2(u64& d, u64 a, u64 b) {
    asm("fma.rn.f32x2 %0,%1,%2,%0;" : "+l"(d) : "l"(a), "l"(b));
}
__device__ __forceinline__ float2 u2f(u64 v) {
    float2 f; asm("mov.b64 {%0,%1},%2;" : "=f"(f.x), "=f"(f.y) : "l"(v)); return f;
}

// ---------------- launch 1: all weight transposes (fused) ----------------
// grid 1792 x 256
__global__ void prep_kernel(const float* __restrict__ wq,
                            const float* __restrict__ wkv,
                            const float* __restrict__ wout,
                            const float* __restrict__ cw) {
    int bid = blockIdx.x, t = threadIdx.x;
    if (bid < 512) {                       // twout: k = 0..511
        int k = bid;
        g_woutT[k * 256 + t] = wout[t * 512 + k];
    } else if (bid < 768) {                // twq: k = 0..255 (256 blocks)
        int k = bid - 512;
        g_wqT[k * 512 + t]       = wq[t * 256 + k];
        g_wqT[k * 512 + t + 256] = wq[(t + 256) * 256 + k];
    } else if (bid < 1024) {               // twkv: k = 0..255
        int k = bid - 768;
        #pragma unroll
        for (int u = 0; u < 4; u++)
            g_wkvT[k * 1024 + t + u * 256] = wkv[(size_t)(t + u * 256) * 256 + k];
    } else {                               // tcw: idx = 0..767
        int idx = bid - 1024;
        int tap = idx >> 8, i = idx & 255;
        g_cwT[tap * 65536 + i * 256 + t] = cw[t * 768 + i * 3 + tap];
    }
}

// ---------------- launch 2: fused pattern double-LN + kv projection ----------------
__device__ __forceinline__ float block_reduce_sum256(float v, float* scratch) {
    #pragma unroll
    for (int o = 16; o; o >>= 1) v += __shfl_xor_sync(0xffffffffu, v, o);
    int w = threadIdx.x >> 5;
    if ((threadIdx.x & 31) == 0) scratch[w] = v;
    __syncthreads();
    if (threadIdx.x < 32) {
        float s = (threadIdx.x < 8) ? scratch[threadIdx.x] : 0.f;
        #pragma unroll
        for (int o = 4; o; o >>= 1) s += __shfl_xor_sync(0xffffffffu, s, o);
        if (threadIdx.x == 0) scratch[0] = s;
    }
    __syncthreads();
    float r = scratch[0];
    __syncthreads();
    return r;
}

__global__ void kv_kernel(const float* __restrict__ pattern) {
    __shared__ float scr[8];
    __shared__ float pr[D];
    int p = blockIdx.x, t = threadIdx.x;
    float v = pattern[p * D + t];
    #pragma unroll
    for (int rep = 0; rep < 2; rep++) {
        float s  = block_reduce_sum256(v, scr);
        float s2 = block_reduce_sum256(v * v, scr);
        float mu  = s * (1.f / D);
        v = (v - mu) * rsqrtf(s2 * (1.f / D) - mu * mu + 1e-5f);
    }
    pr[t] = v;
    __syncthreads();
    float acc[4] = {0.f, 0.f, 0.f, 0.f};
    for (int i = 0; i < D; i++) {
        float xv = pr[i];
        const float* wr = g_wkvT + i * 1024 + t;
        #pragma unroll
        for (int u = 0; u < 4; u++) acc[u] = fmaf(xv, wr[u * 256], acc[u]);
    }
    #pragma unroll
    for (int u = 0; u < 4; u++) {
        int j = t + u * 256;
        int h = j >> 7, r = j & 127;
        if (r < DA) g_kT[(h * DA + r) * PP + p] = acc[u];
        else        g_v [(h * PP + p) * DA + (r - DA)] = acc[u];
    }
}

// ---------------- launch 3: conv + residual + leaky + LN (channel-pair FFMA2) ----------------
__global__ __launch_bounds__(256, 2) void convln_kernel(const float* __restrict__ x,
                                                        const float* __restrict__ conv_b,
                                                        int L) {
    extern __shared__ float sm[];
    float* xs = sm;              // [34][256] rows = tokens t0-2..t0+31
    float* ys = sm + 34 * D;     // [32][256]
    float* st = ys + 32 * D;     // 64
    int tid = threadIdx.x;
    int c2 = tid & 127, th = tid >> 7;
    int t0 = blockIdx.x * 32;
    int pos0 = t0 % L;
    for (int r = 0; r < 34; r++) {
        float v = 0.f;
        if (pos0 + r >= 2) v = x[(size_t)(t0 + r - 2) * D + tid];
        xs[r * D + tid] = v;
    }
    __syncthreads();

    int m0 = th * 16;
    u64 acc[16];
    {
        float2 b = *(const float2*)&conv_b[2 * c2];
        u64 bp = pack2(b.x, b.y);
        #pragma unroll
        for (int j = 0; j < 16; j++) acc[j] = bp;
    }
    const float* cw0 = g_cwT + 2 * c2;
    for (int i = 0; i < D; i++) {
        u64 w0 = *(const u64*)(cw0 +           i * 256);
        u64 w1 = *(const u64*)(cw0 +  65536 + i * 256);
        u64 w2 = *(const u64*)(cw0 + 131072 + i * 256);
        u64 xa = dup2(xs[(m0)     * D + i]);
        u64 xb = dup2(xs[(m0 + 1) * D + i]);
        #pragma unroll
        for (int j = 0; j < 16; j++) {
            u64 xc = dup2(xs[(m0 + j + 2) * D + i]);
            fma2(acc[j], w0, xa);
            fma2(acc[j], w1, xb);
            fma2(acc[j], w2, xc);
            xa = xb; xb = xc;
        }
    }
    #pragma unroll
    for (int j = 0; j < 16; j++) {
        int m = m0 + j;
        float2 f = u2f(acc[j]);
        float2 res = *(const float2*)&xs[(m + 2) * D + 2 * c2];
        float v0 = f.x + res.x, v1 = f.y + res.y;
        v0 = v0 > 0.f ? v0 : 0.01f * v0;
        v1 = v1 > 0.f ? v1 : 0.01f * v1;
        *(float2*)&ys[m * D + 2 * c2] = make_float2(v0, v1);
    }
    __syncthreads();

    int lane = tid & 31, warp = tid >> 5;
    for (int jj = 0; jj < 4; jj++) {
        int m = warp + 8 * jj;
        float s = 0.f, s2 = 0.f;
        #pragma unroll
        for (int q = 0; q < 8; q++) {
            float v = ys[m * D + q * 32 + lane];
            s += v; s2 += v * v;
        }
        #pragma unroll
        for (int o = 16; o; o >>= 1) {
            s  += __shfl_xor_sync(0xffffffffu, s, o);
            s2 += __shfl_xor_sync(0xffffffffu, s2, o);
        }
        if (lane == 0) {
            float mu = s * (1.f / D);
            st[m]      = mu;
            st[32 + m] = rsqrtf(s2 * (1.f / D) - mu * mu + 1e-5f);
        }
    }
    __syncthreads();
    #pragma unroll
    for (int m = 0; m < 32; m++)
        g_xn[(size_t)(t0 + m) * D + tid] = (ys[m * D + tid] - st[m]) * st[32 + m];
}

// ---------------- launch 4 (PROFILED): fused qproj + attention ----------------
__global__ __launch_bounds__(256, 2) void attn_kernel() {
    extern __shared__ float sm[];
    float* qT  = sm;            // [64][33] (reused as attS [32][65])
    float* pr1 = sm + 2112;     // [8][32]
    float* pr2 = sm + 2368;     // [8][32]
    float* buf = sm + 2624;     // 16896 floats: xnT [256][33] then scores [512][33]
    int tid = threadIdx.x, lane = tid & 31, w = tid >> 5;
    int t0 = blockIdx.x * 32, h = blockIdx.y;

    float* xnT = buf;
    for (int r = 0; r < 32; r++) xnT[tid * 33 + r] = g_xn[(size_t)(t0 + r) * D + tid];
    __syncthreads();

    // phase 1: q (cols h*64 + w*8 .. +7)
    u64 qa[4] = {0, 0, 0, 0};
    const float* wqp = g_wqT + h * 64 + w * 8;
    #pragma unroll 4
    for (int k = 0; k < 256; k++) {
        u64 xd = dup2(xnT[k * 33 + lane]);
        const ulonglong2* wp = (const ulonglong2*)(wqp + k * 512);
        ulonglong2 a = wp[0], bq = wp[1];
        fma2(qa[0], a.x, xd); fma2(qa[1], a.y, xd);
        fma2(qa[2], bq.x, xd); fma2(qa[3], bq.y, xd);
    }
    #pragma unroll
    for (int j = 0; j < 4; j++) {
        float2 f = u2f(qa[j]);
        qT[(w * 8 + 2 * j)     * 33 + lane] = f.x;
        qT[(w * 8 + 2 * j + 1) * 33 + lane] = f.y;
    }
    __syncthreads();

    // phase 2: scores, two passes of 32 patterns each (reg-pressure relief)
    float* scores = buf;         // xnT dead
    float mx = -1e30f;
    #pragma unroll
    for (int half = 0; half < 2; half++) {
        int pb = w * 64 + half * 32;
        u64 sa[16];
        #pragma unroll
        for (int j = 0; j < 16; j++) sa[j] = 0;
        const float* kh = g_kT + (size_t)h * DA * PP + pb;
        for (int d = 0; d < DA; d++) {
            u64 qd = dup2(qT[d * 33 + lane]);
            const ulonglong2* kp = (const ulonglong2*)(kh + d * PP);
            #pragma unroll
            for (int j = 0; j < 8; j++) {
                ulonglong2 a = kp[j];
                fma2(sa[2 * j], a.x, qd); fma2(sa[2 * j + 1], a.y, qd);
            }
        }
        #pragma unroll
        for (int j = 0; j < 16; j++) {
            float2 f = u2f(sa[j]);
            mx = fmaxf(mx, fmaxf(f.x, f.y));
            scores[(pb + 2 * j)     * 33 + lane] = f.x;
            scores[(pb + 2 * j + 1) * 33 + lane] = f.y;
        }
    }

    // phase 3: softmax across warps (per token = lane)
    pr1[w * 32 + lane] = mx;
    __syncthreads();
    float gmax = pr1[lane];
    #pragma unroll
    for (int ww = 1; ww < 8; ww++) gmax = fmaxf(gmax, pr1[ww * 32 + lane]);
    float smx = 0.125f * gmax;
    float ssum = 0.f;
    #pragma unroll 8
    for (int j = 0; j < 64; j++) {
        int p = w * 64 + j;
        float e = __expf(fmaf(0.125f, scores[p * 33 + lane], -smx));
        ssum += e;
        scores[p * 33 + lane] = e;
    }
    pr2[w * 32 + lane] = ssum;
    __syncthreads();
    float Ssum = 0.f;
    #pragma unroll
    for (int ww = 0; ww < 8; ww++) Ssum += pr2[ww * 32 + lane];
    float rinv = 1.f / Ssum;

    // phase 4: PV (d-slice w*8..+7)
    u64 va[4] = {0, 0, 0, 0};
    const float* vh = g_v + (size_t)h * PP * DA + w * 8;
    #pragma unroll 4
    for (int p = 0; p < PP; p++) {
        u64 pd = dup2(scores[p * 33 + lane]);
        const ulonglong2* vp = (const ulonglong2*)(vh + p * 64);
        ulonglong2 a = vp[0], bq = vp[1];
        fma2(va[0], a.x, pd); fma2(va[1], a.y, pd);
        fma2(va[2], bq.x, pd); fma2(va[3], bq.y, pd);
    }
    __syncthreads();            // all scores reads done before qT overwrite
    float* attS = qT;           // [32][65]
    #pragma unroll
    for (int j = 0; j < 4; j++) {
        float2 f = u2f(va[j]);
        attS[lane * 65 + w * 8 + 2 * j]     = f.x * rinv;
        attS[lane * 65 + w * 8 + 2 * j + 1] = f.y * rinv;
    }
    __syncthreads();
    for (int k = 0; k < 8; k++) {
        int idx = k * 256 + tid, tok = idx >> 6, c = idx & 63;
        g_att[(size_t)(t0 + tok) * 512 + h * 64 + c] = attS[tok * 65 + c];
    }
}

// ---------------- launch 5: out projection + final LN ----------------
__global__ __launch_bounds__(256, 2) void outln_kernel(const float* __restrict__ bout,
                                                       float* __restrict__ out) {
    extern __shared__ float sm[];
    float* attT = sm;            // [512][33]
    float* ys   = sm + 16896;    // [32][257]
    float* psum = sm + 16896 + 8224;
    float* psq  = psum + 256;
    int tid = threadIdx.x, lane = tid & 31, w = tid >> 5;
    int t0 = blockIdx.x * 32;

    for (int r = 0; r < 32; r++) {
        attT[ tid        * 33 + r] = g_att[(size_t)(t0 + r) * 512 + tid];
        attT[(tid + 256) * 33 + r] = g_att[(size_t)(t0 + r) * 512 + tid + 256];
    }
    __syncthreads();

    u64 acc[16];
    #pragma unroll
    for (int j = 0; j < 16; j++) acc[j] = 0;
    const float* wp0 = g_woutT + w * 32;
    #pragma unroll 2
    for (int k = 0; k < 512; k++) {
        u64 xd = dup2(attT[k * 33 + lane]);
        const ulonglong2* wp = (const ulonglong2*)(wp0 + k * 256);
        #pragma unroll
        for (int j = 0; j < 8; j++) {
            ulonglong2 a = wp[j];
            fma2(acc[2 * j], a.x, xd); fma2(acc[2 * j + 1], a.y, xd);
        }
    }
    float vals[32];
    float s = 0.f, s2 = 0.f;
    #pragma unroll
    for (int j = 0; j < 16; j++) {
        float2 f = u2f(acc[j]);
        int c = w * 32 + 2 * j;
        float v0 = f.x + __ldg(&bout[c]);
        float v1 = f.y + __ldg(&bout[c + 1]);
        vals[2 * j] = v0; vals[2 * j + 1] = v1;
        s += v0 + v1; s2 += v0 * v0 + v1 * v1;
    }
    psum[w * 32 + lane] = s;
    psq [w * 32 + lane] = s2;
    __syncthreads();
    float S = 0.f, S2 = 0.f;
    #pragma unroll
    for (int ww = 0; ww < 8; ww++) { S += psum[ww * 32 + lane]; S2 += psq[ww * 32 + lane]; }
    float mu = S * (1.f / D);
    float rstd = rsqrtf(S2 * (1.f / D) - mu * mu + 1e-5f);
    #pragma unroll
    for (int j = 0; j < 32; j++) ys[lane * 257 + w * 32 + j] = (vals[j] - mu) * rstd;
    __syncthreads();
    for (int k = 0; k < 32; k++) {
        int idx = k * 256 + tid, tok = idx >> 8, c = idx & 255;
        out[(size_t)(t0 + tok) * 256 + c] = ys[tok * 257 + c];
    }
}

// ---------------- launch ----------------
extern "C" void kernel_launch(void* const* d_in, const int* in_sizes, int n_in,
                              void* d_out, int out_size) {
    const float* x       = (const float*)d_in[0];
    const float* conv_w  = (const float*)d_in[1];
    const float* conv_b  = (const float*)d_in[2];
    const float* pattern = (const float*)d_in[3];
    const float* wq      = (const float*)d_in[4];
    const float* wkv     = (const float*)d_in[5];
    const float* wout    = (const float*)d_in[6];
    const float* bout    = (const float*)d_in[7];

    int T = in_sizes[0] / D;
    int B = in_sizes[8] - 1;
    int L = T / B;

    int convln_smem = (34 * D + 32 * D + 64) * 4;
    int attn_smem   = (2112 + 256 + 256 + 16896) * 4;
    int outln_smem  = (16896 + 8224 + 512) * 4;
    cudaFuncSetAttribute(convln_kernel, cudaFuncAttributeMaxDynamicSharedMemorySize, convln_smem);
    cudaFuncSetAttribute(attn_kernel,   cudaFuncAttributeMaxDynamicSharedMemorySize, attn_smem);
    cudaFuncSetAttribute(outln_kernel,  cudaFuncAttributeMaxDynamicSharedMemorySize, outln_smem);

    prep_kernel <<<1792, 256>>>(wq, wkv, wout, conv_w);       // launch 1
    kv_kernel   <<<PP, 256>>>(pattern);                       // launch 2
    convln_kernel<<<T / 32, 256, convln_smem>>>(x, conv_b, L);// launch 3
    dim3 ag(T / 32, HH);
    attn_kernel <<<ag, 256, attn_smem>>>();                   // launch 4 (profiled)
    outln_kernel<<<T / 32, 256, outln_smem>>>(bout, (float*)d_out); // launch 5
}

// round 6
// speedup vs baseline: 2.2439x; 1.5826x over previous
#include <cuda_runtime.h>

#define D   256
#define PP  512
#define HH  8
#define DA  64
#define TMAX 65536
typedef unsigned long long u64;

// ---------------- device scratch ----------------
__device__ float g_kT[HH * DA * PP];              // [h*64+d][p]
__device__ float g_v [HH * PP * DA];              // [h*512+p][d]
__device__ float g_xn [(size_t)TMAX * D];
__device__ float g_att[(size_t)TMAX * HH * DA];
__device__ float g_wqT  [D * 512];                // [k][j]
__device__ float g_woutT[512 * D];                // [k][c]
__device__ float g_cwT  [3 * D * D];              // [tap][i][c]
__device__ float g_wkvT [D * 1024];               // [k][j]

// ---------------- f32x2 helpers ----------------
__device__ __forceinline__ u64 pack2(float x, float y) {
    u64 r; asm("mov.b64 %0,{%1,%2};" : "=l"(r) : "f"(x), "f"(y)); return r;
}
__device__ __forceinline__ u64 dup2(float x) { return pack2(x, x); }
__device__ __forceinline__ void fma2(u64& d, u64 a, u64 b) {
    asm("fma.rn.f32x2 %0,%1,%2,%0;" : "+l"(d) : "l"(a), "l"(b));
}
__device__ __forceinline__ float2 u2f(u64 v) {
    float2 f; asm("mov.b64 {%0,%1},%2;" : "=f"(f.x), "=f"(f.y) : "l"(v)); return f;
}

// ---------------- launch 1: all weight transposes ----------------
__global__ void prep_kernel(const float* __restrict__ wq,
                            const float* __restrict__ wkv,
                            const float* __restrict__ wout,
                            const float* __restrict__ cw) {
    int bid = blockIdx.x, t = threadIdx.x;
    if (bid < 512) {                       // twout: k = 0..511
        int k = bid;
        g_woutT[k * 256 + t] = wout[t * 512 + k];
    } else if (bid < 768) {                // twq: k = 0..255
        int k = bid - 512;
        g_wqT[k * 512 + t]       = wq[t * 256 + k];
        g_wqT[k * 512 + t + 256] = wq[(t + 256) * 256 + k];
    } else if (bid < 1024) {               // twkv: k = 0..255
        int k = bid - 768;
        #pragma unroll
        for (int u = 0; u < 4; u++)
            g_wkvT[k * 1024 + t + u * 256] = wkv[(size_t)(t + u * 256) * 256 + k];
    } else {                               // tcw
        int idx = bid - 1024;
        int tap = idx >> 8, i = idx & 255;
        g_cwT[tap * 65536 + i * 256 + t] = cw[t * 768 + i * 3 + tap];
    }
}

// ---------------- launch 2: pattern double-LN + kv projection ----------------
__device__ __forceinline__ float block_reduce_sum256(float v, float* scratch) {
    #pragma unroll
    for (int o = 16; o; o >>= 1) v += __shfl_xor_sync(0xffffffffu, v, o);
    int w = threadIdx.x >> 5;
    if ((threadIdx.x & 31) == 0) scratch[w] = v;
    __syncthreads();
    if (threadIdx.x < 32) {
        float s = (threadIdx.x < 8) ? scratch[threadIdx.x] : 0.f;
        #pragma unroll
        for (int o = 4; o; o >>= 1) s += __shfl_xor_sync(0xffffffffu, s, o);
        if (threadIdx.x == 0) scratch[0] = s;
    }
    __syncthreads();
    float r = scratch[0];
    __syncthreads();
    return r;
}

__global__ void kv_kernel(const float* __restrict__ pattern) {
    __shared__ float scr[8];
    __shared__ float pr[D];
    int p = blockIdx.x, t = threadIdx.x;
    float v = pattern[p * D + t];
    #pragma unroll
    for (int rep = 0; rep < 2; rep++) {
        float s  = block_reduce_sum256(v, scr);
        float s2 = block_reduce_sum256(v * v, scr);
        float mu  = s * (1.f / D);
        v = (v - mu) * rsqrtf(s2 * (1.f / D) - mu * mu + 1e-5f);
    }
    pr[t] = v;
    __syncthreads();
    float acc[4] = {0.f, 0.f, 0.f, 0.f};
    for (int i = 0; i < D; i++) {
        float xv = pr[i];
        const float* wr = g_wkvT + i * 1024 + t;
        #pragma unroll
        for (int u = 0; u < 4; u++) acc[u] = fmaf(xv, wr[u * 256], acc[u]);
    }
    #pragma unroll
    for (int u = 0; u < 4; u++) {
        int j = t + u * 256;
        int h = j >> 7, r = j & 127;
        if (r < DA) g_kT[(h * DA + r) * PP + p] = acc[u];
        else        g_v [(h * PP + p) * DA + (r - DA)] = acc[u];
    }
}

// ---------------- launch 3: conv + residual + leaky + LN ----------------
__global__ __launch_bounds__(256, 2) void convln_kernel(const float* __restrict__ x,
                                                        const float* __restrict__ conv_b,
                                                        int L) {
    extern __shared__ float sm[];
    float* xs = sm;              // [34][256]
    float* ys = sm + 34 * D;     // [32][256]
    float* st = ys + 32 * D;     // 64
    int tid = threadIdx.x;
    int c2 = tid & 127, th = tid >> 7;
    int t0 = blockIdx.x * 32;
    int pos0 = t0 % L;
    for (int r = 0; r < 34; r++) {
        float v = 0.f;
        if (pos0 + r >= 2) v = x[(size_t)(t0 + r - 2) * D + tid];
        xs[r * D + tid] = v;
    }
    __syncthreads();

    int m0 = th * 16;
    u64 acc[16];
    {
        float2 b = *(const float2*)&conv_b[2 * c2];
        u64 bp = pack2(b.x, b.y);
        #pragma unroll
        for (int j = 0; j < 16; j++) acc[j] = bp;
    }
    const float* cw0 = g_cwT + 2 * c2;
    for (int i = 0; i < D; i++) {
        u64 w0 = *(const u64*)(cw0 +           i * 256);
        u64 w1 = *(const u64*)(cw0 +  65536 + i * 256);
        u64 w2 = *(const u64*)(cw0 + 131072 + i * 256);
        u64 xa = dup2(xs[(m0)     * D + i]);
        u64 xb = dup2(xs[(m0 + 1) * D + i]);
        #pragma unroll
        for (int j = 0; j < 16; j++) {
            u64 xc = dup2(xs[(m0 + j + 2) * D + i]);
            fma2(acc[j], w0, xa);
            fma2(acc[j], w1, xb);
            fma2(acc[j], w2, xc);
            xa = xb; xb = xc;
        }
    }
    #pragma unroll
    for (int j = 0; j < 16; j++) {
        int m = m0 + j;
        float2 f = u2f(acc[j]);
        float2 res = *(const float2*)&xs[(m + 2) * D + 2 * c2];
        float v0 = f.x + res.x, v1 = f.y + res.y;
        v0 = v0 > 0.f ? v0 : 0.01f * v0;
        v1 = v1 > 0.f ? v1 : 0.01f * v1;
        *(float2*)&ys[m * D + 2 * c2] = make_float2(v0, v1);
    }
    __syncthreads();

    int lane = tid & 31, warp = tid >> 5;
    for (int jj = 0; jj < 4; jj++) {
        int m = warp + 8 * jj;
        float s = 0.f, s2 = 0.f;
        #pragma unroll
        for (int q = 0; q < 8; q++) {
            float v = ys[m * D + q * 32 + lane];
            s += v; s2 += v * v;
        }
        #pragma unroll
        for (int o = 16; o; o >>= 1) {
            s  += __shfl_xor_sync(0xffffffffu, s, o);
            s2 += __shfl_xor_sync(0xffffffffu, s2, o);
        }
        if (lane == 0) {
            float mu = s * (1.f / D);
            st[m]      = mu;
            st[32 + m] = rsqrtf(s2 * (1.f / D) - mu * mu + 1e-5f);
        }
    }
    __syncthreads();
    #pragma unroll
    for (int m = 0; m < 32; m++)
        g_xn[(size_t)(t0 + m) * D + tid] = (ys[m * D + tid] - st[m]) * st[32 + m];
}

// ---------------- launch 4 (PROFILED): fused qproj + attention, register-tiled ----------------
// grid (T/32, 8); 256 threads
// smem: qT [64][36] | rb [32] | buf = xnT [256][36] aliased with probsT [32][516]
__global__ __launch_bounds__(256, 2) void attn_kernel() {
    extern __shared__ float sm[];
    float* qT     = sm;            // 2304 floats
    float* rb     = sm + 2304;     // 32
    float* buf    = sm + 2336;     // max(9216, 16512) = 16512
    int tid = threadIdx.x, lane = tid & 31;
    int t0 = blockIdx.x * 32, h = blockIdx.y;

    // ---- stage xnT [k][tok], stride 36 ----
    float* xnT = buf;
    #pragma unroll 4
    for (int r = 0; r < 32; r++) xnT[tid * 36 + r] = g_xn[(size_t)(t0 + r) * D + tid];
    __syncthreads();

    // ---- phase 1: q-proj. thread: colpair 2c, tokens 4g..4g+3 ----
    {
        int c = tid & 31, g = tid >> 5;
        u64 qa[4] = {0, 0, 0, 0};           // [col][tokpair]
        const float* wqp = g_wqT + h * 64 + 2 * c;
        #pragma unroll 4
        for (int k = 0; k < 256; k++) {
            ulonglong2 A = *(const ulonglong2*)&xnT[k * 36 + 4 * g];   // (t0,t1),(t2,t3)
            float2 bf = *(const float2*)(wqp + (size_t)k * 512);
            u64 b0 = dup2(bf.x), b1 = dup2(bf.y);
            fma2(qa[0], A.x, b0); fma2(qa[1], A.y, b0);
            fma2(qa[2], A.x, b1); fma2(qa[3], A.y, b1);
        }
        #pragma unroll
        for (int cs = 0; cs < 2; cs++)
            #pragma unroll
            for (int tp = 0; tp < 2; tp++) {
                float2 f = u2f(qa[cs * 2 + tp]);
                qT[(2 * c + cs) * 36 + 4 * g + 2 * tp]     = f.x;
                qT[(2 * c + cs) * 36 + 4 * g + 2 * tp + 1] = f.y;
            }
    }
    __syncthreads();

    // ---- phase 2: scores + exp (no max needed: |s|*0.125 is O(1), fp32-safe) ----
    // thread: pats pq + pass*256 + 64j (j=0..3), tokens tg*8..tg*8+7
    float* probsT = buf;            // [32][516], xnT dead
    {
        int pq = tid & 63, tg = tid >> 6;
        #pragma unroll
        for (int pass = 0; pass < 2; pass++) {
            u64 acc[16];            // [j][tokpair]
            #pragma unroll
            for (int i = 0; i < 16; i++) acc[i] = 0;
            const float* kh = g_kT + ((size_t)h * 64) * 512 + pq + pass * 256;
            #pragma unroll 2
            for (int d = 0; d < 64; d++) {
                const float* kr = kh + d * 512;
                u64 b0 = dup2(kr[0]),   b1 = dup2(kr[64]);
                u64 b2 = dup2(kr[128]), b3 = dup2(kr[192]);
                ulonglong2 A0 = *(const ulonglong2*)&qT[d * 36 + tg * 8];
                ulonglong2 A1 = *(const ulonglong2*)&qT[d * 36 + tg * 8 + 4];
                fma2(acc[0],  A0.x, b0); fma2(acc[1],  A0.y, b0);
                fma2(acc[2],  A1.x, b0); fma2(acc[3],  A1.y, b0);
                fma2(acc[4],  A0.x, b1); fma2(acc[5],  A0.y, b1);
                fma2(acc[6],  A1.x, b1); fma2(acc[7],  A1.y, b1);
                fma2(acc[8],  A0.x, b2); fma2(acc[9],  A0.y, b2);
                fma2(acc[10], A1.x, b2); fma2(acc[11], A1.y, b2);
                fma2(acc[12], A0.x, b3); fma2(acc[13], A0.y, b3);
                fma2(acc[14], A1.x, b3); fma2(acc[15], A1.y, b3);
            }
            #pragma unroll
            for (int j = 0; j < 4; j++) {
                int patc = pq + pass * 256 + 64 * j;
                #pragma unroll
                for (int tp = 0; tp < 4; tp++) {
                    float2 f = u2f(acc[j * 4 + tp]);
                    int tok = tg * 8 + 2 * tp;
                    probsT[ tok      * 516 + patc] = __expf(0.125f * f.x);
                    probsT[(tok + 1) * 516 + patc] = __expf(0.125f * f.y);
                }
            }
        }
    }
    __syncthreads();

    // ---- phase 3: per-token prob sums (warp w -> tokens 4w..4w+3) ----
    {
        int w = tid >> 5;
        #pragma unroll
        for (int j = 0; j < 4; j++) {
            int tok = w * 4 + j;
            float s = 0.f;
            #pragma unroll
            for (int i = 0; i < 16; i++) s += probsT[tok * 516 + lane + 32 * i];
            #pragma unroll
            for (int o = 16; o; o >>= 1) s += __shfl_xor_sync(0xffffffffu, s, o);
            if (lane == 0) rb[tok] = 1.f / s;
        }
    }
    __syncthreads();

    // ---- phase 4: PV. thread: tokens tg4*4..+3, d-cols 2dp,2dp+1 (horizontal p-pair accs) ----
    {
        int dp = tid & 31, tg4 = tid >> 5;
        u64 acc[8];                 // [tt][dcol] partial sums over (even p, odd p)
        #pragma unroll
        for (int i = 0; i < 8; i++) acc[i] = 0;
        const float* vh = g_v + ((size_t)h * 512) * 64 + 2 * dp;
        #pragma unroll 2
        for (int p0 = 0; p0 < 512; p0 += 4) {
            float2 v0 = *(const float2*)(vh + (size_t)(p0    ) * 64);
            float2 v1 = *(const float2*)(vh + (size_t)(p0 + 1) * 64);
            float2 v2 = *(const float2*)(vh + (size_t)(p0 + 2) * 64);
            float2 v3 = *(const float2*)(vh + (size_t)(p0 + 3) * 64);
            u64 B0x = pack2(v0.x, v1.x), B0y = pack2(v0.y, v1.y);
            u64 B1x = pack2(v2.x, v3.x), B1y = pack2(v2.y, v3.y);
            #pragma unroll
            for (int tt = 0; tt < 4; tt++) {
                ulonglong2 A = *(const ulonglong2*)&probsT[(tg4 * 4 + tt) * 516 + p0];
                fma2(acc[tt * 2],     A.x, B0x); fma2(acc[tt * 2],     A.y, B1x);
                fma2(acc[tt * 2 + 1], A.x, B0y); fma2(acc[tt * 2 + 1], A.y, B1y);
            }
        }
        #pragma unroll
        for (int tt = 0; tt < 4; tt++) {
            int tok = tg4 * 4 + tt;
            float r = rb[tok];
            float2 f0 = u2f(acc[tt * 2]), f1 = u2f(acc[tt * 2 + 1]);
            *(float2*)&g_att[(size_t)(t0 + tok) * 512 + h * 64 + 2 * dp] =
                make_float2((f0.x + f0.y) * r, (f1.x + f1.y) * r);
        }
    }
}

// ---------------- launch 5: out projection + final LN ----------------
__global__ __launch_bounds__(256, 2) void outln_kernel(const float* __restrict__ bout,
                                                       float* __restrict__ out) {
    extern __shared__ float sm[];
    float* attT = sm;            // [512][33]
    float* ys   = sm + 16896;    // [32][257]
    float* psum = sm + 16896 + 8224;
    float* psq  = psum + 256;
    int tid = threadIdx.x, lane = tid & 31, w = tid >> 5;
    int t0 = blockIdx.x * 32;

    for (int r = 0; r < 32; r++) {
        attT[ tid        * 33 + r] = g_att[(size_t)(t0 + r) * 512 + tid];
        attT[(tid + 256) * 33 + r] = g_att[(size_t)(t0 + r) * 512 + tid + 256];
    }
    __syncthreads();

    u64 acc[16];
    #pragma unroll
    for (int j = 0; j < 16; j++) acc[j] = 0;
    const float* wp0 = g_woutT + w * 32;
    #pragma unroll 2
    for (int k = 0; k < 512; k++) {
        u64 xd = dup2(attT[k * 33 + lane]);
        const ulonglong2* wp = (const ulonglong2*)(wp0 + k * 256);
        #pragma unroll
        for (int j = 0; j < 8; j++) {
            ulonglong2 a = wp[j];
            fma2(acc[2 * j], a.x, xd); fma2(acc[2 * j + 1], a.y, xd);
        }
    }
    float vals[32];
    float s = 0.f, s2 = 0.f;
    #pragma unroll
    for (int j = 0; j < 16; j++) {
        float2 f = u2f(acc[j]);
        int c = w * 32 + 2 * j;
        float v0 = f.x + __ldg(&bout[c]);
        float v1 = f.y + __ldg(&bout[c + 1]);
        vals[2 * j] = v0; vals[2 * j + 1] = v1;
        s += v0 + v1; s2 += v0 * v0 + v1 * v1;
    }
    psum[w * 32 + lane] = s;
    psq [w * 32 + lane] = s2;
    __syncthreads();
    float S = 0.f, S2 = 0.f;
    #pragma unroll
    for (int ww = 0; ww < 8; ww++) { S += psum[ww * 32 + lane]; S2 += psq[ww * 32 + lane]; }
    float mu = S * (1.f / D);
    float rstd = rsqrtf(S2 * (1.f / D) - mu * mu + 1e-5f);
    #pragma unroll
    for (int j = 0; j < 32; j++) ys[lane * 257 + w * 32 + j] = (vals[j] - mu) * rstd;
    __syncthreads();
    for (int k = 0; k < 32; k++) {
        int idx = k * 256 + tid, tok = idx >> 8, c = idx & 255;
        out[(size_t)(t0 + tok) * 256 + c] = ys[tok * 257 + c];
    }
}

// ---------------- launch ----------------
extern "C" void kernel_launch(void* const* d_in, const int* in_sizes, int n_in,
                              void* d_out, int out_size) {
    const float* x       = (const float*)d_in[0];
    const float* conv_w  = (const float*)d_in[1];
    const float* conv_b  = (const float*)d_in[2];
    const float* pattern = (const float*)d_in[3];
    const float* wq      = (const float*)d_in[4];
    const float* wkv     = (const float*)d_in[5];
    const float* wout    = (const float*)d_in[6];
    const float* bout    = (const float*)d_in[7];

    int T = in_sizes[0] / D;
    int B = in_sizes[8] - 1;
    int L = T / B;

    int convln_smem = (34 * D + 32 * D + 64) * 4;
    int attn_smem   = (2304 + 32 + 16512) * 4;                // 75392
    int outln_smem  = (16896 + 8224 + 512) * 4;
    cudaFuncSetAttribute(convln_kernel, cudaFuncAttributeMaxDynamicSharedMemorySize, convln_smem);
    cudaFuncSetAttribute(attn_kernel,   cudaFuncAttributeMaxDynamicSharedMemorySize, attn_smem);
    cudaFuncSetAttribute(outln_kernel,  cudaFuncAttributeMaxDynamicSharedMemorySize, outln_smem);

    prep_kernel <<<1792, 256>>>(wq, wkv, wout, conv_w);        // 1
    kv_kernel   <<<PP, 256>>>(pattern);                        // 2
    convln_kernel<<<T / 32, 256, convln_smem>>>(x, conv_b, L); // 3
    dim3 ag(T / 32, HH);
    attn_kernel <<<ag, 256, attn_smem>>>();                    // 4 (profiled)
    outln_kernel<<<T / 32, 256, outln_smem>>>(bout, (float*)d_out); // 5
}

// round 7
// speedup vs baseline: 2.3804x; 1.0608x over previous
#include <cuda_runtime.h>

#define D   256
#define PP  512
#define HH  8
#define DA  64
#define TMAX 65536
typedef unsigned long long u64;

// ---------------- device scratch ----------------
__device__ float g_kP[HH * 32 * PP * 2];          // [h][d2][p]{d-even,d-odd}
__device__ float g_vP[HH * 256 * DA * 2];         // [h][p2][d]{p-even,p-odd}
__device__ float g_xn [(size_t)TMAX * D];
__device__ float g_att[(size_t)TMAX * HH * DA];
__device__ float g_wqP  [128 * 512 * 2];          // [k2][j]{k-even,k-odd}
__device__ float g_woutP[256 * 256 * 2];          // [k2][c]{k-even,k-odd}
__device__ float g_cwT  [3 * D * D];              // [tap][i][c]
__device__ float g_wkvT [D * 1024];               // [k][j]

// ---------------- f32x2 helpers ----------------
__device__ __forceinline__ u64 pack2(float x, float y) {
    u64 r; asm("mov.b64 %0,{%1,%2};" : "=l"(r) : "f"(x), "f"(y)); return r;
}
__device__ __forceinline__ u64 dup2(float x) { return pack2(x, x); }
__device__ __forceinline__ void fma2(u64& d, u64 a, u64 b) {
    asm("fma.rn.f32x2 %0,%1,%2,%0;" : "+l"(d) : "l"(a), "l"(b));
}
__device__ __forceinline__ float2 u2f(u64 v) {
    float2 f; asm("mov.b64 {%0,%1},%2;" : "=f"(f.x), "=f"(f.y) : "l"(v)); return f;
}

// ---------------- launch 1: weight reshapes ----------------
// grid 1408 x 256
__global__ void prep_kernel(const float* __restrict__ wq,
                            const float* __restrict__ wkv,
                            const float* __restrict__ wout,
                            const float* __restrict__ cw) {
    int bid = blockIdx.x, t = threadIdx.x;
    if (bid < 256) {                       // woutP: k2 = 0..255
        int k2 = bid;
        g_woutP[(k2 * 256 + t) * 2]     = wout[t * 512 + 2 * k2];
        g_woutP[(k2 * 256 + t) * 2 + 1] = wout[t * 512 + 2 * k2 + 1];
    } else if (bid < 384) {                // wqP: k2 = 0..127
        int k2 = bid - 256;
        #pragma unroll
        for (int u = 0; u < 2; u++) {
            int j = t + u * 256;
            g_wqP[(k2 * 512 + j) * 2]     = wq[j * 256 + 2 * k2];
            g_wqP[(k2 * 512 + j) * 2 + 1] = wq[j * 256 + 2 * k2 + 1];
        }
    } else if (bid < 640) {                // wkvT: k = 0..255
        int k = bid - 384;
        #pragma unroll
        for (int u = 0; u < 4; u++)
            g_wkvT[k * 1024 + t + u * 256] = wkv[(size_t)(t + u * 256) * 256 + k];
    } else {                               // cwT: idx = 0..767
        int idx = bid - 640;
        int tap = idx >> 8, i = idx & 255;
        g_cwT[tap * 65536 + i * 256 + t] = cw[t * 768 + i * 3 + tap];
    }
}

// ---------------- launch 2: pattern double-LN + kv projection ----------------
__device__ __forceinline__ float block_reduce_sum256(float v, float* scratch) {
    #pragma unroll
    for (int o = 16; o; o >>= 1) v += __shfl_xor_sync(0xffffffffu, v, o);
    int w = threadIdx.x >> 5;
    if ((threadIdx.x & 31) == 0) scratch[w] = v;
    __syncthreads();
    if (threadIdx.x < 32) {
        float s = (threadIdx.x < 8) ? scratch[threadIdx.x] : 0.f;
        #pragma unroll
        for (int o = 4; o; o >>= 1) s += __shfl_xor_sync(0xffffffffu, s, o);
        if (threadIdx.x == 0) scratch[0] = s;
    }
    __syncthreads();
    float r = scratch[0];
    __syncthreads();
    return r;
}

__global__ void kv_kernel(const float* __restrict__ pattern) {
    __shared__ float scr[8];
    __shared__ float pr[D];
    int p = blockIdx.x, t = threadIdx.x;
    float v = pattern[p * D + t];
    #pragma unroll
    for (int rep = 0; rep < 2; rep++) {
        float s  = block_reduce_sum256(v, scr);
        float s2 = block_reduce_sum256(v * v, scr);
        float mu  = s * (1.f / D);
        v = (v - mu) * rsqrtf(s2 * (1.f / D) - mu * mu + 1e-5f);
    }
    pr[t] = v;
    __syncthreads();
    float acc[4] = {0.f, 0.f, 0.f, 0.f};
    for (int i = 0; i < D; i++) {
        float xv = pr[i];
        const float* wr = g_wkvT + i * 1024 + t;
        #pragma unroll
        for (int u = 0; u < 4; u++) acc[u] = fmaf(xv, wr[u * 256], acc[u]);
    }
    #pragma unroll
    for (int u = 0; u < 4; u++) {
        int j = t + u * 256;
        int h = j >> 7, r = j & 127;
        if (r < DA) {   // K element (p, h, d=r)
            g_kP[((h * 32 + (r >> 1)) * 512 + p) * 2 + (r & 1)] = acc[u];
        } else {        // V element (p, h, d=r-64)
            int dc = r - DA;
            g_vP[((h * 256 + (p >> 1)) * 64 + dc) * 2 + (p & 1)] = acc[u];
        }
    }
}

// ---------------- launch 3: conv + residual + leaky + LN (unchanged) ----------------
__global__ __launch_bounds__(256, 2) void convln_kernel(const float* __restrict__ x,
                                                        const float* __restrict__ conv_b,
                                                        int L) {
    extern __shared__ float sm[];
    float* xs = sm;              // [34][256]
    float* ys = sm + 34 * D;     // [32][256]
    float* st = ys + 32 * D;     // 64
    int tid = threadIdx.x;
    int c2 = tid & 127, th = tid >> 7;
    int t0 = blockIdx.x * 32;
    int pos0 = t0 % L;
    for (int r = 0; r < 34; r++) {
        float v = 0.f;
        if (pos0 + r >= 2) v = x[(size_t)(t0 + r - 2) * D + tid];
        xs[r * D + tid] = v;
    }
    __syncthreads();

    int m0 = th * 16;
    u64 acc[16];
    {
        float2 b = *(const float2*)&conv_b[2 * c2];
        u64 bp = pack2(b.x, b.y);
        #pragma unroll
        for (int j = 0; j < 16; j++) acc[j] = bp;
    }
    const float* cw0 = g_cwT + 2 * c2;
    for (int i = 0; i < D; i++) {
        u64 w0 = *(const u64*)(cw0 +           i * 256);
        u64 w1 = *(const u64*)(cw0 +  65536 + i * 256);
        u64 w2 = *(const u64*)(cw0 + 131072 + i * 256);
        u64 xa = dup2(xs[(m0)     * D + i]);
        u64 xb = dup2(xs[(m0 + 1) * D + i]);
        #pragma unroll
        for (int j = 0; j < 16; j++) {
            u64 xc = dup2(xs[(m0 + j + 2) * D + i]);
            fma2(acc[j], w0, xa);
            fma2(acc[j], w1, xb);
            fma2(acc[j], w2, xc);
            xa = xb; xb = xc;
        }
    }
    #pragma unroll
    for (int j = 0; j < 16; j++) {
        int m = m0 + j;
        float2 f = u2f(acc[j]);
        float2 res = *(const float2*)&xs[(m + 2) * D + 2 * c2];
        float v0 = f.x + res.x, v1 = f.y + res.y;
        v0 = v0 > 0.f ? v0 : 0.01f * v0;
        v1 = v1 > 0.f ? v1 : 0.01f * v1;
        *(float2*)&ys[m * D + 2 * c2] = make_float2(v0, v1);
    }
    __syncthreads();

    int lane = tid & 31, warp = tid >> 5;
    for (int jj = 0; jj < 4; jj++) {
        int m = warp + 8 * jj;
        float s = 0.f, s2 = 0.f;
        #pragma unroll
        for (int q = 0; q < 8; q++) {
            float v = ys[m * D + q * 32 + lane];
            s += v; s2 += v * v;
        }
        #pragma unroll
        for (int o = 16; o; o >>= 1) {
            s  += __shfl_xor_sync(0xffffffffu, s, o);
            s2 += __shfl_xor_sync(0xffffffffu, s2, o);
        }
        if (lane == 0) {
            float mu = s * (1.f / D);
            st[m]      = mu;
            st[32 + m] = rsqrtf(s2 * (1.f / D) - mu * mu + 1e-5f);
        }
    }
    __syncthreads();
    #pragma unroll
    for (int m = 0; m < 32; m++)
        g_xn[(size_t)(t0 + m) * D + tid] = (ys[m * D + tid] - st[m]) * st[32 + m];
}

// ---------------- launch 4 (PROFILED): fused qproj + attention, horizontal f32x2 ----------------
// grid (T/32, 8); 256 threads
// smem: qs [32][68] | rb [32] | union{ xs [32][260], probsT [32][516] }
__global__ __launch_bounds__(256, 2) void attn_kernel() {
    extern __shared__ float sm[];
    float* qs  = sm;               // 2176
    float* rb  = sm + 2176;        // 32
    float* buf = sm + 2208;        // 16512
    int tid = threadIdx.x, lane = tid & 31, w = tid >> 5;
    int t0 = blockIdx.x * 32, h = blockIdx.y;

    // ---- stage xs token-major [32][260] (f4-aligned rows) ----
    float* xs = buf;
    {
        int tok = tid >> 3, q0 = tid & 7;
        const float4* src = (const float4*)&g_xn[(size_t)(t0 + tok) * D];
        float4* dst = (float4*)&xs[tok * 260];
        #pragma unroll
        for (int i = 0; i < 8; i++) dst[q0 + 8 * i] = src[q0 + 8 * i];
    }
    __syncthreads();

    // ---- phase 1: q-proj. warp w -> toks 4w..4w+3; cols lane, lane+32 ----
    {
        u64 acc[4][2];
        #pragma unroll
        for (int tt = 0; tt < 4; tt++) { acc[tt][0] = 0; acc[tt][1] = 0; }
        const float* wb = g_wqP + (h * 64 + lane) * 2;
        #pragma unroll 2
        for (int k2 = 0; k2 < 128; k2++) {
            u64 B0 = *(const u64*)(wb + k2 * 1024);
            u64 B1 = *(const u64*)(wb + k2 * 1024 + 64);
            #pragma unroll
            for (int tt = 0; tt < 4; tt++) {
                u64 A = *(const u64*)&xs[(4 * w + tt) * 260 + 2 * k2];
                fma2(acc[tt][0], A, B0);
                fma2(acc[tt][1], A, B1);
            }
        }
        #pragma unroll
        for (int tt = 0; tt < 4; tt++) {
            float2 f0 = u2f(acc[tt][0]), f1 = u2f(acc[tt][1]);
            qs[(4 * w + tt) * 68 + lane]      = f0.x + f0.y;
            qs[(4 * w + tt) * 68 + lane + 32] = f1.x + f1.y;
        }
    }
    __syncthreads();

    // ---- phase 2: scores + exp. warp w -> toks 4w..4w+3; pats lane + 32j (+pass*256) ----
    float* probsT = buf;            // xs dead
    #pragma unroll
    for (int pass = 0; pass < 2; pass++) {
        u64 acc[4][8];
        #pragma unroll
        for (int tt = 0; tt < 4; tt++)
            #pragma unroll
            for (int j = 0; j < 8; j++) acc[tt][j] = 0;
        const float* kb = g_kP + (h * 32 * 512 + pass * 256 + lane) * 2;
        for (int d2 = 0; d2 < 32; d2++) {
            const float* kr = kb + d2 * 1024;
            u64 B[8];
            #pragma unroll
            for (int j = 0; j < 8; j++) B[j] = *(const u64*)(kr + j * 64);
            #pragma unroll
            for (int tt = 0; tt < 4; tt++) {
                u64 A = *(const u64*)&qs[(4 * w + tt) * 68 + 2 * d2];
                #pragma unroll
                for (int j = 0; j < 8; j++) fma2(acc[tt][j], A, B[j]);
            }
        }
        #pragma unroll
        for (int tt = 0; tt < 4; tt++)
            #pragma unroll
            for (int j = 0; j < 8; j++) {
                float2 f = u2f(acc[tt][j]);
                probsT[(4 * w + tt) * 516 + pass * 256 + lane + 32 * j] =
                    __expf(0.125f * (f.x + f.y));
            }
    }
    __syncthreads();

    // ---- phase 3: per-token prob sums ----
    #pragma unroll
    for (int tt = 0; tt < 4; tt++) {
        int tok = 4 * w + tt;
        float s = 0.f;
        #pragma unroll
        for (int i = 0; i < 16; i++) s += probsT[tok * 516 + lane + 32 * i];
        #pragma unroll
        for (int o = 16; o; o >>= 1) s += __shfl_xor_sync(0xffffffffu, s, o);
        if (lane == 0) rb[tok] = 1.f / s;
    }
    __syncthreads();

    // ---- phase 4: PV. warp w -> toks 4w..4w+3; d = lane, lane+32 ----
    {
        u64 acc[4][2];
        #pragma unroll
        for (int tt = 0; tt < 4; tt++) { acc[tt][0] = 0; acc[tt][1] = 0; }
        const float* vb = g_vP + (h * 256 * 64 + lane) * 2;
        #pragma unroll 2
        for (int p2 = 0; p2 < 256; p2++) {
            u64 B0 = *(const u64*)(vb + p2 * 128);
            u64 B1 = *(const u64*)(vb + p2 * 128 + 64);
            #pragma unroll
            for (int tt = 0; tt < 4; tt++) {
                u64 A = *(const u64*)&probsT[(4 * w + tt) * 516 + 2 * p2];
                fma2(acc[tt][0], A, B0);
                fma2(acc[tt][1], A, B1);
            }
        }
        #pragma unroll
        for (int tt = 0; tt < 4; tt++) {
            int tok = 4 * w + tt;
            float r = rb[tok];
            float2 f0 = u2f(acc[tt][0]), f1 = u2f(acc[tt][1]);
            g_att[(size_t)(t0 + tok) * 512 + h * 64 + lane]      = (f0.x + f0.y) * r;
            g_att[(size_t)(t0 + tok) * 512 + h * 64 + lane + 32] = (f1.x + f1.y) * r;
        }
    }
}

// ---------------- launch 5: out projection + final LN (horizontal f32x2) ----------------
__global__ __launch_bounds__(256, 2) void outln_kernel(const float* __restrict__ bout,
                                                       float* __restrict__ out) {
    extern __shared__ float sm[];
    float* as_ = sm;             // [32][516]
    int tid = threadIdx.x, lane = tid & 31, w = tid >> 5;
    int t0 = blockIdx.x * 32;

    {   // stage att rows token-major
        int tok = tid >> 3, q0 = tid & 7;
        const float4* src = (const float4*)&g_att[(size_t)(t0 + tok) * 512];
        float4* dst = (float4*)&as_[tok * 516];
        #pragma unroll
        for (int i = 0; i < 16; i++) dst[q0 + 8 * i] = src[q0 + 8 * i];
    }
    __syncthreads();

    // warp w -> toks 4w..4w+3; cols lane + 32*cj
    u64 acc[4][8];
    #pragma unroll
    for (int tt = 0; tt < 4; tt++)
        #pragma unroll
        for (int j = 0; j < 8; j++) acc[tt][j] = 0;
    const float* wb = g_woutP + lane * 2;
    for (int k2 = 0; k2 < 256; k2++) {
        const float* wr = wb + k2 * 512;
        u64 B[8];
        #pragma unroll
        for (int j = 0; j < 8; j++) B[j] = *(const u64*)(wr + j * 64);
        #pragma unroll
        for (int tt = 0; tt < 4; tt++) {
            u64 A = *(const u64*)&as_[(4 * w + tt) * 516 + 2 * k2];
            #pragma unroll
            for (int j = 0; j < 8; j++) fma2(acc[tt][j], A, B[j]);
        }
    }
    // epilogue: bias + per-token LN (token fully within warp) + store
    #pragma unroll
    for (int tt = 0; tt < 4; tt++) {
        int tok = 4 * w + tt;
        float vals[8];
        float s = 0.f, s2 = 0.f;
        #pragma unroll
        for (int j = 0; j < 8; j++) {
            float2 f = u2f(acc[tt][j]);
            float v = f.x + f.y + __ldg(&bout[lane + 32 * j]);
            vals[j] = v;
            s += v; s2 += v * v;
        }
        #pragma unroll
        for (int o = 16; o; o >>= 1) {
            s  += __shfl_xor_sync(0xffffffffu, s, o);
            s2 += __shfl_xor_sync(0xffffffffu, s2, o);
        }
        float mu = s * (1.f / D);
        float rstd = rsqrtf(s2 * (1.f / D) - mu * mu + 1e-5f);
        #pragma unroll
        for (int j = 0; j < 8; j++)
            out[(size_t)(t0 + tok) * D + lane + 32 * j] = (vals[j] - mu) * rstd;
    }
}

// ---------------- launch ----------------
extern "C" void kernel_launch(void* const* d_in, const int* in_sizes, int n_in,
                              void* d_out, int out_size) {
    const float* x       = (const float*)d_in[0];
    const float* conv_w  = (const float*)d_in[1];
    const float* conv_b  = (const float*)d_in[2];
    const float* pattern = (const float*)d_in[3];
    const float* wq      = (const float*)d_in[4];
    const float* wkv     = (const float*)d_in[5];
    const float* wout    = (const float*)d_in[6];
    const float* bout    = (const float*)d_in[7];

    int T = in_sizes[0] / D;
    int B = in_sizes[8] - 1;
    int L = T / B;

    int convln_smem = (34 * D + 32 * D + 64) * 4;     // 67840
    int attn_smem   = (2176 + 32 + 16512) * 4;        // 74880
    int outln_smem  = (32 * 516) * 4;                 // 66048
    cudaFuncSetAttribute(convln_kernel, cudaFuncAttributeMaxDynamicSharedMemorySize, convln_smem);
    cudaFuncSetAttribute(attn_kernel,   cudaFuncAttributeMaxDynamicSharedMemorySize, attn_smem);
    cudaFuncSetAttribute(outln_kernel,  cudaFuncAttributeMaxDynamicSharedMemorySize, outln_smem);

    prep_kernel <<<1408, 256>>>(wq, wkv, wout, conv_w);        // 1
    kv_kernel   <<<PP, 256>>>(pattern);                        // 2
    convln_kernel<<<T / 32, 256, convln_smem>>>(x, conv_b, L); // 3
    dim3 ag(T / 32, HH);
    attn_kernel <<<ag, 256, attn_smem>>>();                    // 4 (profiled)
    outln_kernel<<<T / 32, 256, outln_smem>>>(bout, (float*)d_out); // 5
}

// round 8
// speedup vs baseline: 2.6073x; 1.0953x over previous
#include <cuda_runtime.h>

#define D   256
#define PP  512
#define HH  8
#define DA  64
#define TMAX 65536
typedef unsigned long long u64;

// ---------------- device scratch ----------------
__device__ float g_kP  [HH * 32 * PP * 2];        // [h][d2][p]{d-even,d-odd}  (p contiguous pairs)
__device__ float g_vP4 [HH * 128 * DA * 4];       // [h][p4][d]{p0,p1,p2,p3}
__device__ float g_xn  [(size_t)TMAX * D];
__device__ float g_att [(size_t)TMAX * HH * DA];
__device__ float g_wqP4  [64 * 512 * 4];          // [k4][j]{k0..k3}
__device__ float g_woutP4[128 * 256 * 4];         // [k4][c]{k0..k3}
__device__ float g_cwT  [3 * D * D];              // [tap][i][c]
__device__ float g_wkvT [D * 1024];               // [k][j]

// ---------------- f32x2 helpers ----------------
__device__ __forceinline__ u64 pack2(float x, float y) {
    u64 r; asm("mov.b64 %0,{%1,%2};" : "=l"(r) : "f"(x), "f"(y)); return r;
}
__device__ __forceinline__ u64 dup2(float x) { return pack2(x, x); }
__device__ __forceinline__ void fma2(u64& d, u64 a, u64 b) {
    asm("fma.rn.f32x2 %0,%1,%2,%0;" : "+l"(d) : "l"(a), "l"(b));
}
__device__ __forceinline__ float2 u2f(u64 v) {
    float2 f; asm("mov.b64 {%0,%1},%2;" : "=f"(f.x), "=f"(f.y) : "l"(v)); return f;
}

// ---------------- launch 1: weight reshapes ----------------
// grid 1216 x 256
__global__ void prep_kernel(const float* __restrict__ wq,
                            const float* __restrict__ wkv,
                            const float* __restrict__ wout,
                            const float* __restrict__ cw) {
    int bid = blockIdx.x, t = threadIdx.x;
    if (bid < 128) {                       // woutP4: k4 = 0..127
        int k4 = bid;
        #pragma unroll
        for (int kk = 0; kk < 4; kk++)
            g_woutP4[(k4 * 256 + t) * 4 + kk] = wout[t * 512 + 4 * k4 + kk];
    } else if (bid < 192) {                // wqP4: k4 = 0..63
        int k4 = bid - 128;
        #pragma unroll
        for (int u = 0; u < 2; u++) {
            int j = t + u * 256;
            #pragma unroll
            for (int kk = 0; kk < 4; kk++)
                g_wqP4[(k4 * 512 + j) * 4 + kk] = wq[j * 256 + 4 * k4 + kk];
        }
    } else if (bid < 448) {                // wkvT: k = 0..255
        int k = bid - 192;
        #pragma unroll
        for (int u = 0; u < 4; u++)
            g_wkvT[k * 1024 + t + u * 256] = wkv[(size_t)(t + u * 256) * 256 + k];
    } else {                               // cwT: idx = 0..767
        int idx = bid - 448;
        int tap = idx >> 8, i = idx & 255;
        g_cwT[tap * 65536 + i * 256 + t] = cw[t * 768 + i * 3 + tap];
    }
}

// ---------------- launch 2: pattern double-LN + kv projection ----------------
__device__ __forceinline__ float block_reduce_sum256(float v, float* scratch) {
    #pragma unroll
    for (int o = 16; o; o >>= 1) v += __shfl_xor_sync(0xffffffffu, v, o);
    int w = threadIdx.x >> 5;
    if ((threadIdx.x & 31) == 0) scratch[w] = v;
    __syncthreads();
    if (threadIdx.x < 32) {
        float s = (threadIdx.x < 8) ? scratch[threadIdx.x] : 0.f;
        #pragma unroll
        for (int o = 4; o; o >>= 1) s += __shfl_xor_sync(0xffffffffu, s, o);
        if (threadIdx.x == 0) scratch[0] = s;
    }
    __syncthreads();
    float r = scratch[0];
    __syncthreads();
    return r;
}

__global__ void kv_kernel(const float* __restrict__ pattern) {
    __shared__ float scr[8];
    __shared__ float pr[D];
    int p = blockIdx.x, t = threadIdx.x;
    float v = pattern[p * D + t];
    #pragma unroll
    for (int rep = 0; rep < 2; rep++) {
        float s  = block_reduce_sum256(v, scr);
        float s2 = block_reduce_sum256(v * v, scr);
        float mu  = s * (1.f / D);
        v = (v - mu) * rsqrtf(s2 * (1.f / D) - mu * mu + 1e-5f);
    }
    pr[t] = v;
    __syncthreads();
    float acc[4] = {0.f, 0.f, 0.f, 0.f};
    for (int i = 0; i < D; i++) {
        float xv = pr[i];
        const float* wr = g_wkvT + i * 1024 + t;
        #pragma unroll
        for (int u = 0; u < 4; u++) acc[u] = fmaf(xv, wr[u * 256], acc[u]);
    }
    #pragma unroll
    for (int u = 0; u < 4; u++) {
        int j = t + u * 256;
        int h = j >> 7, r = j & 127;
        if (r < DA) {   // K element (p, h, d=r)
            g_kP[((h * 32 + (r >> 1)) * 512 + p) * 2 + (r & 1)] = acc[u];
        } else {        // V element (p, h, d=r-64)
            int dc = r - DA;
            g_vP4[((h * 128 + (p >> 2)) * 64 + dc) * 4 + (p & 3)] = acc[u];
        }
    }
}

// ---------------- launch 3: conv + residual + leaky + LN (unchanged) ----------------
__global__ __launch_bounds__(256, 2) void convln_kernel(const float* __restrict__ x,
                                                        const float* __restrict__ conv_b,
                                                        int L) {
    extern __shared__ float sm[];
    float* xs = sm;              // [34][256]
    float* ys = sm + 34 * D;     // [32][256]
    float* st = ys + 32 * D;     // 64
    int tid = threadIdx.x;
    int c2 = tid & 127, th = tid >> 7;
    int t0 = blockIdx.x * 32;
    int pos0 = t0 % L;
    for (int r = 0; r < 34; r++) {
        float v = 0.f;
        if (pos0 + r >= 2) v = x[(size_t)(t0 + r - 2) * D + tid];
        xs[r * D + tid] = v;
    }
    __syncthreads();

    int m0 = th * 16;
    u64 acc[16];
    {
        float2 b = *(const float2*)&conv_b[2 * c2];
        u64 bp = pack2(b.x, b.y);
        #pragma unroll
        for (int j = 0; j < 16; j++) acc[j] = bp;
    }
    const float* cw0 = g_cwT + 2 * c2;
    for (int i = 0; i < D; i++) {
        u64 w0 = *(const u64*)(cw0 +           i * 256);
        u64 w1 = *(const u64*)(cw0 +  65536 + i * 256);
        u64 w2 = *(const u64*)(cw0 + 131072 + i * 256);
        u64 xa = dup2(xs[(m0)     * D + i]);
        u64 xb = dup2(xs[(m0 + 1) * D + i]);
        #pragma unroll
        for (int j = 0; j < 16; j++) {
            u64 xc = dup2(xs[(m0 + j + 2) * D + i]);
            fma2(acc[j], w0, xa);
            fma2(acc[j], w1, xb);
            fma2(acc[j], w2, xc);
            xa = xb; xb = xc;
        }
    }
    #pragma unroll
    for (int j = 0; j < 16; j++) {
        int m = m0 + j;
        float2 f = u2f(acc[j]);
        float2 res = *(const float2*)&xs[(m + 2) * D + 2 * c2];
        float v0 = f.x + res.x, v1 = f.y + res.y;
        v0 = v0 > 0.f ? v0 : 0.01f * v0;
        v1 = v1 > 0.f ? v1 : 0.01f * v1;
        *(float2*)&ys[m * D + 2 * c2] = make_float2(v0, v1);
    }
    __syncthreads();

    int lane = tid & 31, warp = tid >> 5;
    for (int jj = 0; jj < 4; jj++) {
        int m = warp + 8 * jj;
        float s = 0.f, s2 = 0.f;
        #pragma unroll
        for (int q = 0; q < 8; q++) {
            float v = ys[m * D + q * 32 + lane];
            s += v; s2 += v * v;
        }
        #pragma unroll
        for (int o = 16; o; o >>= 1) {
            s  += __shfl_xor_sync(0xffffffffu, s, o);
            s2 += __shfl_xor_sync(0xffffffffu, s2, o);
        }
        if (lane == 0) {
            float mu = s * (1.f / D);
            st[m]      = mu;
            st[32 + m] = rsqrtf(s2 * (1.f / D) - mu * mu + 1e-5f);
        }
    }
    __syncthreads();
    #pragma unroll
    for (int m = 0; m < 32; m++)
        g_xn[(size_t)(t0 + m) * D + tid] = (ys[m * D + tid] - st[m]) * st[32 + m];
}

// ---------------- launch 4 (PROFILED): fused qproj + attention, 128-bit loads ----------------
// grid (T/32, 8); 256 threads
// smem: qs [32][68] | rb [32] | union{ xs [32][260], probsT [32][516] }
__global__ __launch_bounds__(256, 2) void attn_kernel() {
    extern __shared__ float sm[];
    float* qs  = sm;               // 2176
    float* rb  = sm + 2176;        // 32
    float* buf = sm + 2208;        // 16512
    int tid = threadIdx.x, lane = tid & 31, w = tid >> 5;
    int t0 = blockIdx.x * 32, h = blockIdx.y;

    // ---- stage xs token-major [32][260] ----
    float* xs = buf;
    {
        int tok = tid >> 3, q0 = tid & 7;
        const float4* src = (const float4*)&g_xn[(size_t)(t0 + tok) * D];
        float4* dst = (float4*)&xs[tok * 260];
        #pragma unroll
        for (int i = 0; i < 8; i++) dst[q0 + 8 * i] = src[q0 + 8 * i];
    }
    __syncthreads();

    // ---- phase 1: q-proj. warp w -> toks 4w..4w+3; cols lane, lane+32 ----
    {
        u64 acc[4][2];
        #pragma unroll
        for (int tt = 0; tt < 4; tt++) { acc[tt][0] = 0; acc[tt][1] = 0; }
        const float* wb = g_wqP4 + (h * 64 + lane) * 4;
        #pragma unroll 2
        for (int k4 = 0; k4 < 64; k4++) {
            const float* wr = wb + k4 * 2048;
            ulonglong2 B0 = *(const ulonglong2*)(wr);          // col lane, k 4k4..+3
            ulonglong2 B1 = *(const ulonglong2*)(wr + 128);    // col lane+32
            #pragma unroll
            for (int tt = 0; tt < 4; tt++) {
                ulonglong2 A = *(const ulonglong2*)&xs[(4 * w + tt) * 260 + 4 * k4];
                fma2(acc[tt][0], A.x, B0.x); fma2(acc[tt][0], A.y, B0.y);
                fma2(acc[tt][1], A.x, B1.x); fma2(acc[tt][1], A.y, B1.y);
            }
        }
        #pragma unroll
        for (int tt = 0; tt < 4; tt++) {
            float2 f0 = u2f(acc[tt][0]), f1 = u2f(acc[tt][1]);
            qs[(4 * w + tt) * 68 + lane]      = f0.x + f0.y;
            qs[(4 * w + tt) * 68 + lane + 32] = f1.x + f1.y;
        }
    }
    __syncthreads();

    // ---- phase 2: scores + exp. warp w -> toks 4w..4w+3; pats {4lane..+3, 128+4lane..+3} per pass ----
    float* probsT = buf;            // xs dead
    #pragma unroll
    for (int pass = 0; pass < 2; pass++) {
        u64 acc[4][8];
        #pragma unroll
        for (int tt = 0; tt < 4; tt++)
            #pragma unroll
            for (int j = 0; j < 8; j++) acc[tt][j] = 0;
        const float* kb = g_kP + ((size_t)(h * 32) * 512 + pass * 256 + 4 * lane) * 2;
        for (int d2 = 0; d2 < 32; d2++) {
            const float* kr = kb + d2 * 1024;
            ulonglong2 B0 = *(const ulonglong2*)(kr);          // pats 4lane, 4lane+1
            ulonglong2 B1 = *(const ulonglong2*)(kr + 4);      // pats 4lane+2, +3
            ulonglong2 B2 = *(const ulonglong2*)(kr + 256);    // pats 128+4lane..
            ulonglong2 B3 = *(const ulonglong2*)(kr + 260);
            #pragma unroll
            for (int tt = 0; tt < 4; tt++) {
                u64 A = *(const u64*)&qs[(4 * w + tt) * 68 + 2 * d2];
                fma2(acc[tt][0], A, B0.x); fma2(acc[tt][1], A, B0.y);
                fma2(acc[tt][2], A, B1.x); fma2(acc[tt][3], A, B1.y);
                fma2(acc[tt][4], A, B2.x); fma2(acc[tt][5], A, B2.y);
                fma2(acc[tt][6], A, B3.x); fma2(acc[tt][7], A, B3.y);
            }
        }
        #pragma unroll
        for (int tt = 0; tt < 4; tt++) {
            float4 o0, o1;
            float2 f;
            f = u2f(acc[tt][0]); o0.x = __expf(0.125f * (f.x + f.y));
            f = u2f(acc[tt][1]); o0.y = __expf(0.125f * (f.x + f.y));
            f = u2f(acc[tt][2]); o0.z = __expf(0.125f * (f.x + f.y));
            f = u2f(acc[tt][3]); o0.w = __expf(0.125f * (f.x + f.y));
            f = u2f(acc[tt][4]); o1.x = __expf(0.125f * (f.x + f.y));
            f = u2f(acc[tt][5]); o1.y = __expf(0.125f * (f.x + f.y));
            f = u2f(acc[tt][6]); o1.z = __expf(0.125f * (f.x + f.y));
            f = u2f(acc[tt][7]); o1.w = __expf(0.125f * (f.x + f.y));
            int base = (4 * w + tt) * 516 + pass * 256 + 4 * lane;
            *(float4*)&probsT[base]       = o0;
            *(float4*)&probsT[base + 128] = o1;
        }
    }
    __syncthreads();

    // ---- phase 3: per-token prob sums ----
    #pragma unroll
    for (int tt = 0; tt < 4; tt++) {
        int tok = 4 * w + tt;
        float s = 0.f;
        #pragma unroll
        for (int i = 0; i < 16; i++) s += probsT[tok * 516 + lane + 32 * i];
        #pragma unroll
        for (int o = 16; o; o >>= 1) s += __shfl_xor_sync(0xffffffffu, s, o);
        if (lane == 0) rb[tok] = 1.f / s;
    }
    __syncthreads();

    // ---- phase 4: PV. warp w -> toks 4w..4w+3; d = lane, lane+32 ----
    {
        u64 acc[4][2];
        #pragma unroll
        for (int tt = 0; tt < 4; tt++) { acc[tt][0] = 0; acc[tt][1] = 0; }
        const float* vb = g_vP4 + ((size_t)(h * 128) * 64 + lane) * 4;
        #pragma unroll 2
        for (int p4 = 0; p4 < 128; p4++) {
            const float* vr = vb + p4 * 256;
            ulonglong2 Bd0 = *(const ulonglong2*)(vr);         // col lane: p 4p4..+3
            ulonglong2 Bd1 = *(const ulonglong2*)(vr + 128);   // col lane+32
            #pragma unroll
            for (int tt = 0; tt < 4; tt++) {
                ulonglong2 A = *(const ulonglong2*)&probsT[(4 * w + tt) * 516 + 4 * p4];
                fma2(acc[tt][0], A.x, Bd0.x); fma2(acc[tt][0], A.y, Bd0.y);
                fma2(acc[tt][1], A.x, Bd1.x); fma2(acc[tt][1], A.y, Bd1.y);
            }
        }
        #pragma unroll
        for (int tt = 0; tt < 4; tt++) {
            int tok = 4 * w + tt;
            float r = rb[tok];
            float2 f0 = u2f(acc[tt][0]), f1 = u2f(acc[tt][1]);
            g_att[(size_t)(t0 + tok) * 512 + h * 64 + lane]      = (f0.x + f0.y) * r;
            g_att[(size_t)(t0 + tok) * 512 + h * 64 + lane + 32] = (f1.x + f1.y) * r;
        }
    }
}

// ---------------- launch 5: out projection + final LN (128-bit loads) ----------------
__global__ __launch_bounds__(256, 2) void outln_kernel(const float* __restrict__ bout,
                                                       float* __restrict__ out) {
    extern __shared__ float sm[];
    float* as_ = sm;             // [32][516]
    int tid = threadIdx.x, lane = tid & 31, w = tid >> 5;
    int t0 = blockIdx.x * 32;

    {   // stage att rows token-major
        int tok = tid >> 3, q0 = tid & 7;
        const float4* src = (const float4*)&g_att[(size_t)(t0 + tok) * 512];
        float4* dst = (float4*)&as_[tok * 516];
        #pragma unroll
        for (int i = 0; i < 16; i++) dst[q0 + 8 * i] = src[q0 + 8 * i];
    }
    __syncthreads();

    // warp w -> toks 4w..4w+3; cols lane + 32j
    u64 acc[4][8];
    #pragma unroll
    for (int tt = 0; tt < 4; tt++)
        #pragma unroll
        for (int j = 0; j < 8; j++) acc[tt][j] = 0;
    const float* wb = g_woutP4 + lane * 4;
    for (int k4 = 0; k4 < 128; k4++) {
        const float* wr = wb + k4 * 1024;
        ulonglong2 B[8];
        #pragma unroll
        for (int j = 0; j < 8; j++) B[j] = *(const ulonglong2*)(wr + j * 128);
        #pragma unroll
        for (int tt = 0; tt < 4; tt++) {
            ulonglong2 A = *(const ulonglong2*)&as_[(4 * w + tt) * 516 + 4 * k4];
            #pragma unroll
            for (int j = 0; j < 8; j++) {
                fma2(acc[tt][j], A.x, B[j].x);
                fma2(acc[tt][j], A.y, B[j].y);
            }
        }
    }
    // epilogue: bias + per-token LN + store
    #pragma unroll
    for (int tt = 0; tt < 4; tt++) {
        int tok = 4 * w + tt;
        float vals[8];
        float s = 0.f, s2 = 0.f;
        #pragma unroll
        for (int j = 0; j < 8; j++) {
            float2 f = u2f(acc[tt][j]);
            float v = f.x + f.y + __ldg(&bout[lane + 32 * j]);
            vals[j] = v;
            s += v; s2 += v * v;
        }
        #pragma unroll
        for (int o = 16; o; o >>= 1) {
            s  += __shfl_xor_sync(0xffffffffu, s, o);
            s2 += __shfl_xor_sync(0xffffffffu, s2, o);
        }
        float mu = s * (1.f / D);
        float rstd = rsqrtf(s2 * (1.f / D) - mu * mu + 1e-5f);
        #pragma unroll
        for (int j = 0; j < 8; j++)
            out[(size_t)(t0 + tok) * D + lane + 32 * j] = (vals[j] - mu) * rstd;
    }
}

// ---------------- launch ----------------
extern "C" void kernel_launch(void* const* d_in, const int* in_sizes, int n_in,
                              void* d_out, int out_size) {
    const float* x       = (const float*)d_in[0];
    const float* conv_w  = (const float*)d_in[1];
    const float* conv_b  = (const float*)d_in[2];
    const float* pattern = (const float*)d_in[3];
    const float* wq      = (const float*)d_in[4];
    const float* wkv     = (const float*)d_in[5];
    const float* wout    = (const float*)d_in[6];
    const float* bout    = (const float*)d_in[7];

    int T = in_sizes[0] / D;
    int B = in_sizes[8] - 1;
    int L = T / B;

    int convln_smem = (34 * D + 32 * D + 64) * 4;     // 67840
    int attn_smem   = (2176 + 32 + 16512) * 4;        // 74880
    int outln_smem  = (32 * 516) * 4;                 // 66048
    cudaFuncSetAttribute(convln_kernel, cudaFuncAttributeMaxDynamicSharedMemorySize, convln_smem);
    cudaFuncSetAttribute(attn_kernel,   cudaFuncAttributeMaxDynamicSharedMemorySize, attn_smem);
    cudaFuncSetAttribute(outln_kernel,  cudaFuncAttributeMaxDynamicSharedMemorySize, outln_smem);

    prep_kernel <<<1216, 256>>>(wq, wkv, wout, conv_w);        // 1
    kv_kernel   <<<PP, 256>>>(pattern);                        // 2
    convln_kernel<<<T / 32, 256, convln_smem>>>(x, conv_b, L); // 3
    dim3 ag(T / 32, HH);
    attn_kernel <<<ag, 256, attn_smem>>>();                    // 4 (profiled)
    outln_kernel<<<T / 32, 256, outln_smem>>>(bout, (float*)d_out); // 5
}

// round 10
// speedup vs baseline: 2.9630x; 1.1364x over previous
#include <cuda_runtime.h>

#define D   256
#define PP  512
#define HH  8
#define DA  64
#define TMAX 65536
typedef unsigned long long u64;

// ---------------- device scratch ----------------
__device__ float g_kQ  [HH * 16 * PP * 4];        // [h][d4][p]{d0..d3}
__device__ float g_vP4 [HH * 128 * DA * 4];       // [h][p4][d]{p0..p3}
__device__ float g_xn  [(size_t)TMAX * D];
__device__ float g_att [(size_t)TMAX * HH * DA];
__device__ float g_wqP4  [64 * 512 * 4];          // [k4][j]{k0..k3}
__device__ float g_woutP4[128 * 256 * 4];         // [k4][c]{k0..k3}
__device__ float g_cwT  [3 * D * D];              // [tap][i][c]
__device__ float g_wkvT [D * 1024];               // [k][j]

// ---------------- f32x2 helpers ----------------
__device__ __forceinline__ u64 pack2(float x, float y) {
    u64 r; asm("mov.b64 %0,{%1,%2};" : "=l"(r) : "f"(x), "f"(y)); return r;
}
__device__ __forceinline__ u64 dup2(float x) { return pack2(x, x); }
__device__ __forceinline__ void fma2(u64& d, u64 a, u64 b) {
    asm("fma.rn.f32x2 %0,%1,%2,%0;" : "+l"(d) : "l"(a), "l"(b));
}
__device__ __forceinline__ float2 u2f(u64 v) {
    float2 f; asm("mov.b64 {%0,%1},%2;" : "=f"(f.x), "=f"(f.y) : "l"(v)); return f;
}

// ---------------- launch 1: weight reshapes ----------------
// grid 1216 x 256
__global__ void prep_kernel(const float* __restrict__ wq,
                            const float* __restrict__ wkv,
                            const float* __restrict__ wout,
                            const float* __restrict__ cw) {
    int bid = blockIdx.x, t = threadIdx.x;
    if (bid < 128) {                       // woutP4
        int k4 = bid;
        #pragma unroll
        for (int kk = 0; kk < 4; kk++)
            g_woutP4[(k4 * 256 + t) * 4 + kk] = wout[t * 512 + 4 * k4 + kk];
    } else if (bid < 192) {                // wqP4
        int k4 = bid - 128;
        #pragma unroll
        for (int u = 0; u < 2; u++) {
            int j = t + u * 256;
            #pragma unroll
            for (int kk = 0; kk < 4; kk++)
                g_wqP4[(k4 * 512 + j) * 4 + kk] = wq[j * 256 + 4 * k4 + kk];
        }
    } else if (bid < 448) {                // wkvT
        int k = bid - 192;
        #pragma unroll
        for (int u = 0; u < 4; u++)
            g_wkvT[k * 1024 + t + u * 256] = wkv[(size_t)(t + u * 256) * 256 + k];
    } else {                               // cwT
        int idx = bid - 448;
        int tap = idx >> 8, i = idx & 255;
        g_cwT[tap * 65536 + i * 256 + t] = cw[t * 768 + i * 3 + tap];
    }
}

// ---------------- launch 2: pattern double-LN + kv projection ----------------
__device__ __forceinline__ float block_reduce_sum256(float v, float* scratch) {
    #pragma unroll
    for (int o = 16; o; o >>= 1) v += __shfl_xor_sync(0xffffffffu, v, o);
    int w = threadIdx.x >> 5;
    if ((threadIdx.x & 31) == 0) scratch[w] = v;
    __syncthreads();
    if (threadIdx.x < 32) {
        float s = (threadIdx.x < 8) ? scratch[threadIdx.x] : 0.f;
        #pragma unroll
        for (int o = 4; o; o >>= 1) s += __shfl_xor_sync(0xffffffffu, s, o);
        if (threadIdx.x == 0) scratch[0] = s;
    }
    __syncthreads();
    float r = scratch[0];
    __syncthreads();
    return r;
}

__global__ void kv_kernel(const float* __restrict__ pattern) {
    __shared__ float scr[8];
    __shared__ float pr[D];
    int p = blockIdx.x, t = threadIdx.x;
    float v = pattern[p * D + t];
    #pragma unroll
    for (int rep = 0; rep < 2; rep++) {
        float s  = block_reduce_sum256(v, scr);
        float s2 = block_reduce_sum256(v * v, scr);
        float mu  = s * (1.f / D);
        v = (v - mu) * rsqrtf(s2 * (1.f / D) - mu * mu + 1e-5f);
    }
    pr[t] = v;
    __syncthreads();
    float acc[4] = {0.f, 0.f, 0.f, 0.f};
    for (int i = 0; i < D; i++) {
        float xv = pr[i];
        const float* wr = g_wkvT + i * 1024 + t;
        #pragma unroll
        for (int u = 0; u < 4; u++) acc[u] = fmaf(xv, wr[u * 256], acc[u]);
    }
    #pragma unroll
    for (int u = 0; u < 4; u++) {
        int j = t + u * 256;
        int h = j >> 7, r = j & 127;
        if (r < DA) {   // K element (p, h, d=r)
            g_kQ[(((h * 16) + (r >> 2)) * 512 + p) * 4 + (r & 3)] = acc[u];
        } else {        // V element (p, h, d=r-64)
            int dc = r - DA;
            g_vP4[((h * 128 + (p >> 2)) * 64 + dc) * 4 + (p & 3)] = acc[u];
        }
    }
}

// ---------------- launch 3: conv + residual + leaky + LN ----------------
__global__ __launch_bounds__(256, 2) void convln_kernel(const float* __restrict__ x,
                                                        const float* __restrict__ conv_b,
                                                        int L) {
    extern __shared__ float sm[];
    float* xs = sm;              // [34][256]
    float* ys = sm + 34 * D;     // [32][256]
    float* st = ys + 32 * D;     // 64
    int tid = threadIdx.x;
    int c2 = tid & 127, th = tid >> 7;
    int t0 = blockIdx.x * 32;
    int pos0 = t0 % L;
    for (int r = 0; r < 34; r++) {
        float v = 0.f;
        if (pos0 + r >= 2) v = x[(size_t)(t0 + r - 2) * D + tid];
        xs[r * D + tid] = v;
    }
    __syncthreads();

    int m0 = th * 16;
    u64 acc[16];
    {
        float2 b = *(const float2*)&conv_b[2 * c2];
        u64 bp = pack2(b.x, b.y);
        #pragma unroll
        for (int j = 0; j < 16; j++) acc[j] = bp;
    }
    const float* cw0 = g_cwT + 2 * c2;
    for (int i = 0; i < D; i++) {
        u64 w0 = *(const u64*)(cw0 +           i * 256);
        u64 w1 = *(const u64*)(cw0 +  65536 + i * 256);
        u64 w2 = *(const u64*)(cw0 + 131072 + i * 256);
        u64 xa = dup2(xs[(m0)     * D + i]);
        u64 xb = dup2(xs[(m0 + 1) * D + i]);
        #pragma unroll
        for (int j = 0; j < 16; j++) {
            u64 xc = dup2(xs[(m0 + j + 2) * D + i]);
            fma2(acc[j], w0, xa);
            fma2(acc[j], w1, xb);
            fma2(acc[j], w2, xc);
            xa = xb; xb = xc;
        }
    }
    #pragma unroll
    for (int j = 0; j < 16; j++) {
        int m = m0 + j;
        float2 f = u2f(acc[j]);
        float2 res = *(const float2*)&xs[(m + 2) * D + 2 * c2];
        float v0 = f.x + res.x, v1 = f.y + res.y;
        v0 = v0 > 0.f ? v0 : 0.01f * v0;
        v1 = v1 > 0.f ? v1 : 0.01f * v1;
        *(float2*)&ys[m * D + 2 * c2] = make_float2(v0, v1);
    }
    __syncthreads();

    int lane = tid & 31, warp = tid >> 5;
    for (int jj = 0; jj < 4; jj++) {
        int m = warp + 8 * jj;
        float s = 0.f, s2 = 0.f;
        #pragma unroll
        for (int q = 0; q < 8; q++) {
            float v = ys[m * D + q * 32 + lane];
            s += v; s2 += v * v;
        }
        #pragma unroll
        for (int o = 16; o; o >>= 1) {
            s  += __shfl_xor_sync(0xffffffffu, s, o);
            s2 += __shfl_xor_sync(0xffffffffu, s2, o);
        }
        if (lane == 0) {
            float mu = s * (1.f / D);
            st[m]      = mu;
            st[32 + m] = rsqrtf(s2 * (1.f / D) - mu * mu + 1e-5f);
        }
    }
    __syncthreads();
    #pragma unroll
    for (int m = 0; m < 32; m++)
        g_xn[(size_t)(t0 + m) * D + tid] = (ys[m * D + tid] - st[m]) * st[32 + m];
}

// ---------------- launch 4 (PROFILED): fused qproj + attention ----------------
// grid (T/32, 8); 256 threads
// smem: qs [32][68] | rb [32] | part [2][32][64] | union{ xs [32][260], probsT [32][516] }
__global__ __launch_bounds__(256, 2) void attn_kernel() {
    extern __shared__ float sm[];
    float* qs   = sm;               // 2176
    float* rb   = sm + 2176;        // 32
    float* part = sm + 2208;        // 4096
    float* buf  = sm + 6304;        // 16512
    int tid = threadIdx.x, lane = tid & 31, w = tid >> 5;
    int t0 = blockIdx.x * 32, h = blockIdx.y;

    // ---- stage xs token-major [32][260] ----
    float* xs = buf;
    {
        int tok = tid >> 3, q0 = tid & 7;
        const float4* src = (const float4*)&g_xn[(size_t)(t0 + tok) * D];
        float4* dst = (float4*)&xs[tok * 260];
        #pragma unroll
        for (int i = 0; i < 8; i++) dst[q0 + 8 * i] = src[q0 + 8 * i];
    }
    __syncthreads();

    // ---- phase 1: q-proj. warp w -> toks 4w..4w+3; cols lane, lane+32 ----
    {
        u64 acc[4][2];
        #pragma unroll
        for (int tt = 0; tt < 4; tt++) { acc[tt][0] = 0; acc[tt][1] = 0; }
        const float* wb = g_wqP4 + (h * 64 + lane) * 4;
        #pragma unroll 2
        for (int k4 = 0; k4 < 64; k4++) {
            const float* wr = wb + k4 * 2048;
            ulonglong2 B0 = *(const ulonglong2*)(wr);
            ulonglong2 B1 = *(const ulonglong2*)(wr + 128);
            #pragma unroll
            for (int tt = 0; tt < 4; tt++) {
                ulonglong2 A = *(const ulonglong2*)&xs[(4 * w + tt) * 260 + 4 * k4];
                fma2(acc[tt][0], A.x, B0.x); fma2(acc[tt][0], A.y, B0.y);
                fma2(acc[tt][1], A.x, B1.x); fma2(acc[tt][1], A.y, B1.y);
            }
        }
        #pragma unroll
        for (int tt = 0; tt < 4; tt++) {
            float2 f0 = u2f(acc[tt][0]), f1 = u2f(acc[tt][1]);
            qs[(4 * w + tt) * 68 + lane]      = f0.x + f0.y;
            qs[(4 * w + tt) * 68 + lane + 32] = f1.x + f1.y;
        }
    }
    __syncthreads();

    // ---- phase 2: scores + exp ----
    // warp w: toks 8(w&3)..+7; slice ps=(w>>2); 2 passes over 128-pat quarters:
    //   pats = ps*256 + pass*128 + lane + 32j, j=0..3
    float* probsT = buf;            // xs dead
    {
        int tg = w & 3, ps = w >> 2;
        int tokb = tg * 8;
        const float* kb = g_kQ + ((size_t)(h * 16) * 512 + ps * 256 + lane) * 4;
        #pragma unroll
        for (int pass = 0; pass < 2; pass++) {
            u64 acc[8][4];
            #pragma unroll
            for (int tt = 0; tt < 8; tt++)
                #pragma unroll
                for (int j = 0; j < 4; j++) acc[tt][j] = 0;
            for (int d4 = 0; d4 < 16; d4++) {
                const float* kr = kb + d4 * 2048 + pass * 512;
                ulonglong2 B[4];
                #pragma unroll
                for (int j = 0; j < 4; j++) B[j] = *(const ulonglong2*)(kr + j * 128);
                #pragma unroll
                for (int tt = 0; tt < 8; tt++) {
                    ulonglong2 A = *(const ulonglong2*)&qs[(tokb + tt) * 68 + 4 * d4];
                    #pragma unroll
                    for (int j = 0; j < 4; j++) {
                        fma2(acc[tt][j], A.x, B[j].x);
                        fma2(acc[tt][j], A.y, B[j].y);
                    }
                }
            }
            #pragma unroll
            for (int tt = 0; tt < 8; tt++)
                #pragma unroll
                for (int j = 0; j < 4; j++) {
                    float2 f = u2f(acc[tt][j]);
                    probsT[(tokb + tt) * 516 + ps * 256 + pass * 128 + lane + 32 * j] =
                        __expf(0.125f * (f.x + f.y));
                }
        }
    }
    __syncthreads();

    // ---- phase 3: per-token prob sums (warp w -> toks 4w..4w+3) ----
    #pragma unroll
    for (int tt = 0; tt < 4; tt++) {
        int tok = 4 * w + tt;
        float s = 0.f;
        #pragma unroll
        for (int i = 0; i < 16; i++) s += probsT[tok * 516 + lane + 32 * i];
        #pragma unroll
        for (int o = 16; o; o >>= 1) s += __shfl_xor_sync(0xffffffffu, s, o);
        if (lane == 0) rb[tok] = 1.f / s;
    }
    __syncthreads();

    // ---- phase 4: PV. warp w: toks 8(w&3)..+7; p-half (w>>2); d = lane, lane+32 ----
    {
        int tg = w & 3, ph = w >> 2;
        int tokb = tg * 8;
        u64 acc[8][2];
        #pragma unroll
        for (int tt = 0; tt < 8; tt++) { acc[tt][0] = 0; acc[tt][1] = 0; }
        const float* vb = g_vP4 + ((size_t)(h * 128 + ph * 64) * 64 + lane) * 4;
        #pragma unroll 2
        for (int p4 = 0; p4 < 64; p4++) {
            const float* vr = vb + p4 * 256;
            ulonglong2 B0 = *(const ulonglong2*)(vr);          // d = lane
            ulonglong2 B1 = *(const ulonglong2*)(vr + 128);    // d = lane+32
            #pragma unroll
            for (int tt = 0; tt < 8; tt++) {
                ulonglong2 A = *(const ulonglong2*)&probsT[(tokb + tt) * 516 + ph * 256 + 4 * p4];
                fma2(acc[tt][0], A.x, B0.x); fma2(acc[tt][0], A.y, B0.y);
                fma2(acc[tt][1], A.x, B1.x); fma2(acc[tt][1], A.y, B1.y);
            }
        }
        #pragma unroll
        for (int tt = 0; tt < 8; tt++) {
            float2 f0 = u2f(acc[tt][0]), f1 = u2f(acc[tt][1]);
            part[(ph * 32 + tokb + tt) * 64 + lane]      = f0.x + f0.y;
            part[(ph * 32 + tokb + tt) * 64 + lane + 32] = f1.x + f1.y;
        }
    }
    __syncthreads();

    // ---- phase 5: combine p-halves, scale, store ----
    #pragma unroll
    for (int k = 0; k < 8; k++) {
        int idx = k * 256 + tid;
        int tok = idx >> 6, d = idx & 63;
        float v = (part[(tok) * 64 + d] + part[(32 + tok) * 64 + d]) * rb[tok];
        g_att[(size_t)(t0 + tok) * 512 + h * 64 + d] = v;
    }
}

// ---------------- launch 5: out projection + final LN ----------------
__global__ __launch_bounds__(256, 2) void outln_kernel(const float* __restrict__ bout,
                                                       float* __restrict__ out) {
    extern __shared__ float sm[];
    float* as_ = sm;             // [32][516]
    int tid = threadIdx.x, lane = tid & 31, w = tid >> 5;
    int t0 = blockIdx.x * 32;

    {
        int tok = tid >> 3, q0 = tid & 7;
        const float4* src = (const float4*)&g_att[(size_t)(t0 + tok) * 512];
        float4* dst = (float4*)&as_[tok * 516];
        #pragma unroll
        for (int i = 0; i < 16; i++) dst[q0 + 8 * i] = src[q0 + 8 * i];
    }
    __syncthreads();

    u64 acc[4][8];
    #pragma unroll
    for (int tt = 0; tt < 4; tt++)
        #pragma unroll
        for (int j = 0; j < 8; j++) acc[tt][j] = 0;
    const float* wb = g_woutP4 + lane * 4;
    for (int k4 = 0; k4 < 128; k4++) {
        const float* wr = wb + k4 * 1024;
        ulonglong2 B[8];
        #pragma unroll
        for (int j = 0; j < 8; j++) B[j] = *(const ulonglong2*)(wr + j * 128);
        #pragma unroll
        for (int tt = 0; tt < 4; tt++) {
            ulonglong2 A = *(const ulonglong2*)&as_[(4 * w + tt) * 516 + 4 * k4];
            #pragma unroll
            for (int j = 0; j < 8; j++) {
                fma2(acc[tt][j], A.x, B[j].x);
                fma2(acc[tt][j], A.y, B[j].y);
            }
        }
    }
    #pragma unroll
    for (int tt = 0; tt < 4; tt++) {
        int tok = 4 * w + tt;
        float vals[8];
        float s = 0.f, s2 = 0.f;
        #pragma unroll
        for (int j = 0; j < 8; j++) {
            float2 f = u2f(acc[tt][j]);
            float v = f.x + f.y + __ldg(&bout[lane + 32 * j]);
            vals[j] = v;
            s += v; s2 += v * v;
        }
        #pragma unroll
        for (int o = 16; o; o >>= 1) {
            s  += __shfl_xor_sync(0xffffffffu, s, o);
            s2 += __shfl_xor_sync(0xffffffffu, s2, o);
        }
        float mu = s * (1.f / D);
        float rstd = rsqrtf(s2 * (1.f / D) - mu * mu + 1e-5f);
        #pragma unroll
        for (int j = 0; j < 8; j++)
            out[(size_t)(t0 + tok) * D + lane + 32 * j] = (vals[j] - mu) * rstd;
    }
}

// ---------------- launch ----------------
extern "C" void kernel_launch(void* const* d_in, const int* in_sizes, int n_in,
                              void* d_out, int out_size) {
    const float* x       = (const float*)d_in[0];
    const float* conv_w  = (const float*)d_in[1];
    const float* conv_b  = (const float*)d_in[2];
    const float* pattern = (const float*)d_in[3];
    const float* wq      = (const float*)d_in[4];
    const float* wkv     = (const float*)d_in[5];
    const float* wout    = (const float*)d_in[6];
    const float* bout    = (const float*)d_in[7];

    int T = in_sizes[0] / D;
    int B = in_sizes[8] - 1;
    int L = T / B;

    int convln_smem = (34 * D + 32 * D + 64) * 4;          // 67840
    int attn_smem   = (2176 + 32 + 4096 + 16512) * 4;      // 91264
    int outln_smem  = (32 * 516) * 4;                      // 66048
    cudaFuncSetAttribute(convln_kernel, cudaFuncAttributeMaxDynamicSharedMemorySize, convln_smem);
    cudaFuncSetAttribute(attn_kernel,   cudaFuncAttributeMaxDynamicSharedMemorySize, attn_smem);
    cudaFuncSetAttribute(outln_kernel,  cudaFuncAttributeMaxDynamicSharedMemorySize, outln_smem);

    prep_kernel <<<1216, 256>>>(wq, wkv, wout, conv_w);        // 1
    kv_kernel   <<<PP, 256>>>(pattern);                        // 2
    convln_kernel<<<T / 32, 256, convln_smem>>>(x, conv_b, L); // 3
    dim3 ag(T / 32, HH);
    attn_kernel <<<ag, 256, attn_smem>>>();                    // 4 (profiled)
    outln_kernel<<<T / 32, 256, outln_smem>>>(bout, (float*)d_out); // 5
}